// round 14
// baseline (speedup 1.0000x reference)
#include <cuda_runtime.h>
#include <stdint.h>
#include <math.h>

#define BB   2048
#define NNB  64
#define HH   128
#define HN   64
#define NSEQ (BB*NNB)

__device__ float g_nf[NSEQ * HN];        // neighbor GRU features
__device__ float g_tf[BB * HH];          // target GRU features
__device__ float g_enc[BB * 8 * HH];     // per-sector MLP output
__device__ float g_f1[BB * 256];         // first final-MLP layer

__device__ __forceinline__ float sigmoidf_(float x) {
    return __fdividef(1.0f, 1.0f + __expf(-x));
}
__device__ __forceinline__ float tanhf_(float x) {
    return __fdividef(2.0f, 1.0f + __expf(-2.0f * x)) - 1.0f;
}
__device__ __forceinline__ uint32_t pack_bf2(float lo, float hi) {
    uint32_t r;
    asm("cvt.rn.bf16x2.f32 %0, %1, %2;" : "=r"(r) : "f"(hi), "f"(lo));
    return r;
}
__device__ __forceinline__ float bf_lo(uint32_t u) { return __uint_as_float(u << 16); }
__device__ __forceinline__ float bf_hi(uint32_t u) { return __uint_as_float(u & 0xFFFF0000u); }

__device__ __forceinline__ void mma16816(float* d, const uint32_t* a, uint2 b) {
    asm volatile("mma.sync.aligned.m16n8k16.row.col.f32.bf16.bf16.f32 "
        "{%0,%1,%2,%3}, {%4,%5,%6,%7}, {%8,%9}, {%0,%1,%2,%3};"
        : "+f"(d[0]), "+f"(d[1]), "+f"(d[2]), "+f"(d[3])
        : "r"(a[0]), "r"(a[1]), "r"(a[2]), "r"(a[3]), "r"(b.x), "r"(b.y));
}

// =============== K1: neighbor GRU via mma.sync bf16x3 (HMMA) ===============
// Warp tile = 16 seqs; per-jt accumulators (12 live) + N-fragment double buffer.
// No forced min-blocks: let ptxas pick registers; 2 blocks/SM if regs <= 128.
#define H_WHI  0                 // u32[24][4][32][2]  24576 B
#define H_WLO  24576             // u32 same           24576 B
#define H_XS   49152             // float2[8][128]      8192 B
#define H_WIH  57344             // float2[192]         1536 B
#define H_BIH  58880             // float[192]           768 B
#define H_BHH  59648             // float[192]           768 B
#define H_SMEM 60416
#define H_NTILE (NSEQ / 128)     // 1024

__global__ __launch_bounds__(256)
void k1_ngru(const float* __restrict__ traj, const float* __restrict__ Wih,
             const float* __restrict__ Whh, const float* __restrict__ bih,
             const float* __restrict__ bhh)
{
    extern __shared__ char sh[];
    uint32_t* WHI = (uint32_t*)(sh + H_WHI);
    uint32_t* WLO = (uint32_t*)(sh + H_WLO);
    float2*   XS2 = (float2*)(sh + H_XS);
    float2*   WIH2= (float2*)(sh + H_WIH);
    float*    BIH = (float*)(sh + H_BIH);
    float*    BHH = (float*)(sh + H_BHH);

    const int tid  = threadIdx.x;
    const int lane = tid & 31;
    const int w    = tid >> 5;
    const int g    = lane >> 2;
    const int tig  = lane & 3;

    // stage Whh fragments (hi/lo bf16 split)
    for (int e = tid; e < 3072; e += 256) {
        int l = e & 31, jtkt = e >> 5;
        int kt = jtkt & 3, jt = jtkt >> 2;
        int j = 8 * jt + (l >> 2);
        #pragma unroll
        for (int r = 0; r < 2; ++r) {
            int k = 16 * kt + 2 * (l & 3) + 8 * r;
            float w0 = Whh[j * 64 + k], w1 = Whh[j * 64 + k + 1];
            uint32_t hi = pack_bf2(w0, w1);
            uint32_t lo = pack_bf2(w0 - bf_lo(hi), w1 - bf_hi(hi));
            WHI[e * 2 + r] = hi;
            WLO[e * 2 + r] = lo;
        }
    }
    if (tid < 192) {
        WIH2[tid] = ((const float2*)Wih)[tid];
        BIH[tid] = bih[tid];
        BHH[tid] = bhh[tid];
    }
    __syncthreads();

    const int sl = w * 16 + g;

    for (int tile = blockIdx.x; tile < H_NTILE; tile += gridDim.x) {
        __syncthreads();
        {
            int s_ = tid >> 1, q0 = (tid & 1) * 2;
            const float4* tp = (const float4*)(traj + (size_t)(tile * 128 + s_) * 16);
            float4 v0 = tp[q0], v1 = tp[q0 + 1];
            XS2[(2 * q0 + 0) * 128 + s_] = make_float2(v0.x, v0.y);
            XS2[(2 * q0 + 1) * 128 + s_] = make_float2(v0.z, v0.w);
            XS2[(2 * q0 + 2) * 128 + s_] = make_float2(v1.x, v1.y);
            XS2[(2 * q0 + 3) * 128 + s_] = make_float2(v1.z, v1.w);
        }
        __syncthreads();

        uint32_t Ahi[4][4], Alo[4][4], Nhi[4][4], Nlo[4][4];
        #pragma unroll
        for (int kt = 0; kt < 4; ++kt)
            #pragma unroll
            for (int r = 0; r < 4; ++r) { Ahi[kt][r] = 0u; Alo[kt][r] = 0u; }

        for (int t = 0; t < 8; ++t) {
            float2 xA = XS2[t * 128 + sl];
            float2 xB = XS2[t * 128 + sl + 8];
            #pragma unroll 2
            for (int jt = 0; jt < 8; ++jt) {
                float dr[4], dz[4], dn[4];
                {
                    float2 b2 = *(const float2*)&BHH[8 * jt + 2 * tig];
                    dr[0] = b2.x; dr[1] = b2.y; dr[2] = b2.x; dr[3] = b2.y;
                    b2 = *(const float2*)&BHH[64 + 8 * jt + 2 * tig];
                    dz[0] = b2.x; dz[1] = b2.y; dz[2] = b2.x; dz[3] = b2.y;
                    b2 = *(const float2*)&BHH[128 + 8 * jt + 2 * tig];
                    dn[0] = b2.x; dn[1] = b2.y; dn[2] = b2.x; dn[3] = b2.y;
                }
                if (t > 0) {
                    #pragma unroll
                    for (int kt = 0; kt < 4; ++kt) {
                        uint2 bh = *(const uint2*)&WHI[((jt * 4 + kt) * 32 + lane) * 2];
                        uint2 bl = *(const uint2*)&WLO[((jt * 4 + kt) * 32 + lane) * 2];
                        mma16816(dr, Ahi[kt], bh);
                        mma16816(dr, Ahi[kt], bl);
                        mma16816(dr, Alo[kt], bh);
                    }
                    #pragma unroll
                    for (int kt = 0; kt < 4; ++kt) {
                        uint2 bh = *(const uint2*)&WHI[(((jt + 8) * 4 + kt) * 32 + lane) * 2];
                        uint2 bl = *(const uint2*)&WLO[(((jt + 8) * 4 + kt) * 32 + lane) * 2];
                        mma16816(dz, Ahi[kt], bh);
                        mma16816(dz, Ahi[kt], bl);
                        mma16816(dz, Alo[kt], bh);
                    }
                    #pragma unroll
                    for (int kt = 0; kt < 4; ++kt) {
                        uint2 bh = *(const uint2*)&WHI[(((jt + 16) * 4 + kt) * 32 + lane) * 2];
                        uint2 bl = *(const uint2*)&WLO[(((jt + 16) * 4 + kt) * 32 + lane) * 2];
                        mma16816(dn, Ahi[kt], bh);
                        mma16816(dn, Ahi[kt], bl);
                        mma16816(dn, Alo[kt], bh);
                    }
                }
                // gates for this i-group
                float4 wr4 = *(const float4*)&WIH2[8 * jt + 2 * tig];
                float4 wz4 = *(const float4*)&WIH2[64 + 8 * jt + 2 * tig];
                float4 wn4 = *(const float4*)&WIH2[128 + 8 * jt + 2 * tig];
                float2 br2 = *(const float2*)&BIH[8 * jt + 2 * tig];
                float2 bz2 = *(const float2*)&BIH[64 + 8 * jt + 2 * tig];
                float2 bn2 = *(const float2*)&BIH[128 + 8 * jt + 2 * tig];
                const int kt = jt >> 1;
                #pragma unroll
                for (int rh = 0; rh < 2; ++rh) {
                    float x0 = rh ? xB.x : xA.x;
                    float x1 = rh ? xB.y : xA.y;
                    const int reg = (jt & 1) * 2 + rh;
                    uint32_t uh = Ahi[kt][reg], ul = Alo[kt][reg];
                    float hold0 = bf_lo(uh) + bf_lo(ul);
                    float hold1 = bf_hi(uh) + bf_hi(ul);
                    float hnew0, hnew1;
                    #pragma unroll
                    for (int c = 0; c < 2; ++c) {
                        float hr = dr[rh * 2 + c];
                        float hz = dz[rh * 2 + c];
                        float hn = dn[rh * 2 + c];
                        float wrx = c ? wr4.z : wr4.x, wry = c ? wr4.w : wr4.y;
                        float wzx = c ? wz4.z : wz4.x, wzy = c ? wz4.w : wz4.y;
                        float wnx = c ? wn4.z : wn4.x, wny = c ? wn4.w : wn4.y;
                        float xr = fmaf(x0, wrx, fmaf(x1, wry, c ? br2.y : br2.x));
                        float xz = fmaf(x0, wzx, fmaf(x1, wzy, c ? bz2.y : bz2.x));
                        float xn = fmaf(x0, wnx, fmaf(x1, wny, c ? bn2.y : bn2.x));
                        float r = sigmoidf_(xr + hr);
                        float z = sigmoidf_(xz + hz);
                        float n = tanhf_(fmaf(r, hn, xn));
                        float hold = c ? hold1 : hold0;
                        float h = fmaf(z, hold - n, n);
                        if (c) hnew1 = h; else hnew0 = h;
                    }
                    if (t < 7) {
                        uint32_t nh = pack_bf2(hnew0, hnew1);
                        uint32_t nl = pack_bf2(hnew0 - bf_lo(nh), hnew1 - bf_hi(nh));
                        Nhi[kt][reg] = nh; Nlo[kt][reg] = nl;
                    } else {
                        int seq = tile * 128 + sl + 8 * rh;
                        *(float2*)&g_nf[(size_t)seq * 64 + 8 * jt + 2 * tig] =
                            make_float2(hnew0, hnew1);
                    }
                }
            }
            if (t < 7) {
                #pragma unroll
                for (int kt = 0; kt < 4; ++kt)
                    #pragma unroll
                    for (int r = 0; r < 4; ++r) {
                        Ahi[kt][r] = Nhi[kt][r];
                        Alo[kt][r] = Nlo[kt][r];
                    }
            }
        }
    }
}

// ============================ K2: target GRU ============================
#define K2_WT  0
#define K2_HP  (K2_WT + 128*385)
#define K2_H   (K2_HP + 3*384)
#define K2_X   (K2_H + 384)
#define K2_WIH (K2_X + 48)
#define K2_BIH (K2_WIH + 768)
#define K2_BHH (K2_BIH + 384)
#define K2_SMEM ((K2_BHH + 384) * 4)

__global__ __launch_bounds__(384)
void k2_tgru(const float* __restrict__ traj, const float* __restrict__ Wih,
             const float* __restrict__ Whh, const float* __restrict__ bih,
             const float* __restrict__ bhh)
{
    extern __shared__ float sm[];
    float *WT = sm + K2_WT, *HP = sm + K2_HP, *H = sm + K2_H, *X = sm + K2_X;
    float *WIH = sm + K2_WIH, *BIH = sm + K2_BIH, *BHH = sm + K2_BHH;
    const int tid = threadIdx.x;

    for (int idx = tid; idx < 384*128; idx += 384)
        WT[(idx & 127) * 385 + (idx >> 7)] = Whh[idx];
    for (int idx = tid; idx < 768; idx += 384) WIH[idx] = Wih[idx];
    BIH[tid] = bih[tid]; BHH[tid] = bhh[tid];
    __syncthreads();

    const int s = tid >> 7, i = tid & 127;

    for (int tile = blockIdx.x; tile < (BB + 2) / 3; tile += gridDim.x) {
        const int seq0 = tile * 3;
        __syncthreads();
        if (tid < 48) {
            int sq = seq0 + tid / 16;
            X[tid] = (sq < BB) ? traj[sq * 16 + (tid & 15)] : 0.0f;
        }
        H[tid] = 0.0f;
        __syncthreads();

        for (int t = 0; t < 8; ++t) {
            {
                float b = BHH[tid];
                float a0 = b, a1 = b, a2 = b;
                #pragma unroll
                for (int k = 0; k < 128; k += 4) {
                    float4 h0 = *reinterpret_cast<const float4*>(H + k);
                    float4 h1 = *reinterpret_cast<const float4*>(H + 128 + k);
                    float4 h2 = *reinterpret_cast<const float4*>(H + 256 + k);
                    float w0 = WT[(k  )*385+tid], w1 = WT[(k+1)*385+tid];
                    float w2 = WT[(k+2)*385+tid], w3 = WT[(k+3)*385+tid];
                    a0 = fmaf(w0,h0.x,fmaf(w1,h0.y,fmaf(w2,h0.z,fmaf(w3,h0.w,a0))));
                    a1 = fmaf(w0,h1.x,fmaf(w1,h1.y,fmaf(w2,h1.z,fmaf(w3,h1.w,a1))));
                    a2 = fmaf(w0,h2.x,fmaf(w1,h2.y,fmaf(w2,h2.z,fmaf(w3,h2.w,a2))));
                }
                HP[tid] = a0; HP[384 + tid] = a1; HP[768 + tid] = a2;
            }
            __syncthreads();
            {
                float x0 = X[s*16 + t*2], x1 = X[s*16 + t*2 + 1];
                float xr = fmaf(x0, WIH[2*i],        fmaf(x1, WIH[2*i+1],        BIH[i]));
                float xz = fmaf(x0, WIH[2*(128+i)],  fmaf(x1, WIH[2*(128+i)+1],  BIH[128+i]));
                float xn = fmaf(x0, WIH[2*(256+i)],  fmaf(x1, WIH[2*(256+i)+1],  BIH[256+i]));
                float r = sigmoidf_(xr + HP[s*384 + i]);
                float z = sigmoidf_(xz + HP[s*384 + 128 + i]);
                float n = tanhf_(xn + r * HP[s*384 + 256 + i]);
                H[s*128 + i] = (1.0f - z) * n + z * H[s*128 + i];
            }
            __syncthreads();
        }
        int sq = seq0 + s;
        if (sq < BB) g_tf[sq * 128 + i] = H[s*128 + i];
    }
}

// =================== K3: sector features + per-sector MLP ===================
#define K3_W1T  0
#define K3_W2T  (K3_W1T + 68*129)
#define K3_NF   (K3_W2T + 128*129)
#define K3_FEAT (K3_NF + 4096)
#define K3_H1   (K3_FEAT + 8*68)
#define K3_WSUM (K3_H1 + 1024)
#define K3_WV   (K3_WSUM + 8)
#define K3_DIST (K3_WV + 64)
#define K3_VAL  (K3_DIST + 64)
#define K3_V0   (K3_VAL + 64)
#define K3_V1   (K3_V0 + 64)
#define K3_SMEM ((K3_V1 + 64) * 4)

__global__ __launch_bounds__(512)
void k3_sector(const float* __restrict__ ttraj, const float* __restrict__ ntraj,
               const float* __restrict__ ang, const float* __restrict__ mask,
               const float* __restrict__ W1, const float* __restrict__ b1,
               const float* __restrict__ W2, const float* __restrict__ b2)
{
    extern __shared__ float smf[];
    __shared__ int SID[64];
    float *W1T = smf + K3_W1T, *W2T = smf + K3_W2T, *NF = smf + K3_NF;
    float *FEAT = smf + K3_FEAT, *H1 = smf + K3_H1, *WSUM = smf + K3_WSUM;
    float *WV = smf + K3_WV, *DIST = smf + K3_DIST, *VAL = smf + K3_VAL;
    float *V0 = smf + K3_V0, *V1 = smf + K3_V1;
    const int tid = threadIdx.x;

    for (int idx = tid; idx < 128*68; idx += 512)
        W1T[(idx % 68) * 129 + (idx / 68)] = W1[idx];
    for (int idx = tid; idx < 128*128; idx += 512)
        W2T[(idx & 127) * 129 + (idx >> 7)] = W2[idx];
    __syncthreads();

    const int s = tid >> 6, i = tid & 63;

    for (int b = blockIdx.x; b < BB; b += gridDim.x) {
        __syncthreads();
        for (int idx = tid; idx < 4096; idx += 512)
            NF[idx] = g_nf[b * 4096 + idx];
        if (tid < 64) {
            const float* base = ntraj + (size_t)(b * 64 + tid) * 16;
            float px = base[14], py = base[15];
            float dx = px - ttraj[b*16 + 14], dy = py - ttraj[b*16 + 15];
            float d = sqrtf(dx*dx + dy*dy);
            DIST[tid] = d;
            V0[tid] = px - base[12];
            V1[tid] = py - base[13];
            int sid = (int)(ang[b*64 + tid] * 1.27323954473516f);
            SID[tid] = min(max(sid, 0), 7);
            float vf = (mask[b*64 + tid] > 0.0f) ? 1.0f : 0.0f;
            VAL[tid] = vf;
            WV[tid] = __expf(-d * 0.1f) * vf;
        }
        __syncthreads();
        if (tid < 8) {
            float cnt = 0.f, dsum = 0.f, v0 = 0.f, v1 = 0.f, ws = 0.f;
            for (int n = 0; n < 64; ++n) {
                bool in = (SID[n] == tid);
                float m = in ? VAL[n] : 0.0f;
                cnt += m; dsum += m * DIST[n]; v0 += m * V0[n]; v1 += m * V1[n];
                ws += in ? WV[n] : 0.0f;
            }
            float safe = fmaxf(cnt, 1.0f);
            bool ne = cnt > 0.0f;
            FEAT[tid*68 + 0] = cnt;
            FEAT[tid*68 + 1] = ne ? dsum / safe : 0.0f;
            FEAT[tid*68 + 2] = ne ? v0 / safe : 0.0f;
            FEAT[tid*68 + 3] = ne ? v1 / safe : 0.0f;
            WSUM[tid] = ws + 1e-8f;
        }
        __syncthreads();
        {
            float acc = 0.0f;
            for (int n = 0; n < 64; ++n) {
                float wm = (SID[n] == s) ? WV[n] : 0.0f;
                acc = fmaf(wm, NF[n*64 + i], acc);
            }
            FEAT[s*68 + 4 + i] = acc / WSUM[s];
        }
        __syncthreads();
        for (int o = tid; o < 1024; o += 512) {
            int os = o >> 7, oj = o & 127;
            float acc = b1[oj];
            #pragma unroll
            for (int k = 0; k < 68; ++k)
                acc = fmaf(FEAT[os*68 + k], W1T[k*129 + oj], acc);
            H1[os*128 + oj] = fmaxf(acc, 0.0f);
        }
        __syncthreads();
        for (int o = tid; o < 1024; o += 512) {
            int os = o >> 7, oj = o & 127;
            float acc = b2[oj];
            #pragma unroll
            for (int k = 0; k < 128; ++k)
                acc = fmaf(H1[os*128 + k], W2T[k*129 + oj], acc);
            g_enc[b * 1024 + o] = fmaxf(acc, 0.0f);
        }
    }
}

// =================== K5: f1 = relu([tf,enc] @ Wf1.T + bf1) ===================
// M-tile 4, grid 512 for better wave balance.
#define K5_PAD 8
#define K5_SMEM ((32*257 + 32*K5_PAD) * 4)

__global__ __launch_bounds__(256)
void k5_f1(const float* __restrict__ Wf1, const float* __restrict__ bf1)
{
    extern __shared__ float k5s[];
    float* Wsh = k5s;
    float* Ash = k5s + 32 * 257;

    const int tid = threadIdx.x;
    const int m0 = blockIdx.x * 4;
    const int jb = tid >> 5, kk = tid & 31;

    float acc[4];
    float bv = bf1[tid];
    #pragma unroll
    for (int r = 0; r < 4; ++r) acc[r] = bv;

    float wreg[32];
    float areg = 0.0f;

    #pragma unroll
    for (int rr = 0; rr < 32; ++rr)
        wreg[rr] = Wf1[(jb + rr * 8) * 1152 + kk];
    if (jb < 4) areg = g_tf[(m0 + jb) * 128 + kk];

    for (int c = 0; c < 36; ++c) {
        __syncthreads();
        #pragma unroll
        for (int rr = 0; rr < 32; ++rr)
            Wsh[kk * 257 + jb + rr * 8] = wreg[rr];
        if (jb < 4) Ash[kk * K5_PAD + jb] = areg;
        __syncthreads();
        if (c < 35) {
            const int k0 = (c + 1) * 32;
            #pragma unroll
            for (int rr = 0; rr < 32; ++rr)
                wreg[rr] = Wf1[(jb + rr * 8) * 1152 + k0 + kk];
            if (jb < 4) {
                int gk = k0 + kk;
                areg = (gk < 128) ? g_tf[(m0 + jb) * 128 + gk]
                                  : g_enc[(m0 + jb) * 1024 + gk - 128];
            }
        }
        #pragma unroll
        for (int q = 0; q < 32; ++q) {
            float w = Wsh[q * 257 + tid];
            float4 a0 = *reinterpret_cast<const float4*>(&Ash[q * K5_PAD]);
            acc[0]=fmaf(w,a0.x,acc[0]); acc[1]=fmaf(w,a0.y,acc[1]);
            acc[2]=fmaf(w,a0.z,acc[2]); acc[3]=fmaf(w,a0.w,acc[3]);
        }
    }
    #pragma unroll
    for (int r = 0; r < 4; ++r)
        g_f1[(m0 + r) * 256 + tid] = fmaxf(acc[r], 0.0f);
}

// =================== K6: f2, f3, LayerNorm ===================
#define K6_W2T 0
#define K6_W3T (K6_W2T + 256*129)
#define K6_F1  (K6_W3T + 128*65)
#define K6_F2  (K6_F1 + 16*257)
#define K6_F3  (K6_F2 + 16*129)
#define K6_MU  (K6_F3 + 1024)
#define K6_RS  (K6_MU + 16)
#define K6_SMEM ((K6_RS + 16) * 4)

__global__ __launch_bounds__(128)
void k6_final(const float* __restrict__ Wf2, const float* __restrict__ bf2,
              const float* __restrict__ Wf3, const float* __restrict__ bf3,
              const float* __restrict__ ln_g, const float* __restrict__ ln_b,
              float* __restrict__ out)
{
    extern __shared__ float smf[];
    float *W2T = smf + K6_W2T, *W3T = smf + K6_W3T, *F1 = smf + K6_F1;
    float *F2 = smf + K6_F2, *F3 = smf + K6_F3, *MU = smf + K6_MU, *RS = smf + K6_RS;
    const int tid = threadIdx.x;
    const int m0 = blockIdx.x * 16;

    for (int idx = tid; idx < 128*256; idx += 128)
        W2T[(idx & 255) * 129 + (idx >> 8)] = Wf2[idx];
    for (int idx = tid; idx < 64*128; idx += 128)
        W3T[(idx & 127) * 65 + (idx >> 7)] = Wf3[idx];
    for (int idx = tid; idx < 16*256; idx += 128)
        F1[(idx >> 8) * 257 + (idx & 255)] = g_f1[m0 * 256 + idx];
    __syncthreads();

    {
        float acc[16];
        float bv = bf2[tid];
        #pragma unroll
        for (int r = 0; r < 16; ++r) acc[r] = bv;
        for (int k = 0; k < 256; ++k) {
            float w = W2T[k * 129 + tid];
            #pragma unroll
            for (int r = 0; r < 16; ++r)
                acc[r] = fmaf(F1[r * 257 + k], w, acc[r]);
        }
        #pragma unroll
        for (int r = 0; r < 16; ++r)
            F2[r * 129 + tid] = fmaxf(acc[r], 0.0f);
    }
    __syncthreads();
    for (int o = tid; o < 1024; o += 128) {
        int r = o >> 6, j = o & 63;
        float acc = bf3[j];
        #pragma unroll
        for (int k = 0; k < 128; ++k)
            acc = fmaf(F2[r * 129 + k], W3T[k * 65 + j], acc);
        F3[o] = fmaxf(acc, 0.0f);
    }
    __syncthreads();
    if (tid < 16) {
        float s0 = 0.f;
        #pragma unroll
        for (int j = 0; j < 64; ++j) s0 += F3[tid*64 + j];
        float mu = s0 * (1.0f / 64.0f);
        float v = 0.f;
        #pragma unroll
        for (int j = 0; j < 64; ++j) { float dd = F3[tid*64 + j] - mu; v = fmaf(dd, dd, v); }
        MU[tid] = mu;
        RS[tid] = rsqrtf(v * (1.0f / 64.0f) + 1e-5f);
    }
    __syncthreads();
    for (int o = tid; o < 1024; o += 128) {
        int r = o >> 6, j = o & 63;
        out[(m0 + r) * 64 + j] = (F3[o] - MU[r]) * RS[r] * ln_g[j] + ln_b[j];
    }
}

// =============================== launch ===============================
extern "C" void kernel_launch(void* const* d_in, const int* in_sizes, int n_in,
                              void* d_out, int out_size)
{
    const float* ttraj = (const float*)d_in[0];
    const float* ntraj = (const float*)d_in[1];
    const float* ang   = (const float*)d_in[2];
    const float* mask  = (const float*)d_in[3];
    const float* Wih_t = (const float*)d_in[4];
    const float* Whh_t = (const float*)d_in[5];
    const float* bih_t = (const float*)d_in[6];
    const float* bhh_t = (const float*)d_in[7];
    const float* Wih_n = (const float*)d_in[8];
    const float* Whh_n = (const float*)d_in[9];
    const float* bih_n = (const float*)d_in[10];
    const float* bhh_n = (const float*)d_in[11];
    const float* W1  = (const float*)d_in[12];
    const float* b1  = (const float*)d_in[13];
    const float* W2  = (const float*)d_in[14];
    const float* b2  = (const float*)d_in[15];
    const float* Wf1 = (const float*)d_in[16];
    const float* bf1 = (const float*)d_in[17];
    const float* Wf2 = (const float*)d_in[18];
    const float* bf2 = (const float*)d_in[19];
    const float* Wf3 = (const float*)d_in[20];
    const float* bf3 = (const float*)d_in[21];
    const float* ln_g = (const float*)d_in[22];
    const float* ln_b = (const float*)d_in[23];
    float* out = (float*)d_out;

    cudaFuncSetAttribute(k1_ngru,   cudaFuncAttributeMaxDynamicSharedMemorySize, H_SMEM);
    cudaFuncSetAttribute(k2_tgru,   cudaFuncAttributeMaxDynamicSharedMemorySize, K2_SMEM);
    cudaFuncSetAttribute(k3_sector, cudaFuncAttributeMaxDynamicSharedMemorySize, K3_SMEM);
    cudaFuncSetAttribute(k5_f1,     cudaFuncAttributeMaxDynamicSharedMemorySize, K5_SMEM);
    cudaFuncSetAttribute(k6_final,  cudaFuncAttributeMaxDynamicSharedMemorySize, K6_SMEM);

    k1_ngru<<<296, 256, H_SMEM>>>(ntraj, Wih_n, Whh_n, bih_n, bhh_n);
    k2_tgru<<<148, 384, K2_SMEM>>>(ttraj, Wih_t, Whh_t, bih_t, bhh_t);
    k3_sector<<<296, 512, K3_SMEM>>>(ttraj, ntraj, ang, mask, W1, b1, W2, b2);
    k5_f1<<<512, 256, K5_SMEM>>>(Wf1, bf1);
    k6_final<<<128, 128, K6_SMEM>>>(Wf2, bf2, Wf3, bf3, ln_g, ln_b, out);
}

// round 15
// speedup vs baseline: 1.1198x; 1.1198x over previous
#include <cuda_runtime.h>
#include <stdint.h>
#include <math.h>

#define BB   2048
#define NNB  64
#define HH   128
#define HN   64
#define NSEQ (BB*NNB)

__device__ float g_nf[NSEQ * HN];        // neighbor GRU features
__device__ float g_tf[BB * HH];          // target GRU features
__device__ float g_enc[BB * 8 * HH];     // per-sector MLP output
__device__ float g_f1[BB * 256];         // first final-MLP layer

// fast activations: hardware tanh (MUFU.TANH), sigmoid via tanh identity
__device__ __forceinline__ float tanh_fast(float x) {
    float y; asm("tanh.approx.f32 %0, %1;" : "=f"(y) : "f"(x)); return y;
}
__device__ __forceinline__ float sigmoid_fast(float x) {
    return fmaf(0.5f, tanh_fast(0.5f * x), 0.5f);
}
__device__ __forceinline__ uint32_t pack_bf2(float lo, float hi) {
    uint32_t r;
    asm("cvt.rn.bf16x2.f32 %0, %1, %2;" : "=r"(r) : "f"(hi), "f"(lo));
    return r;
}
__device__ __forceinline__ float bf_lo(uint32_t u) { return __uint_as_float(u << 16); }
__device__ __forceinline__ float bf_hi(uint32_t u) { return __uint_as_float(u & 0xFFFF0000u); }

__device__ __forceinline__ void mma16816(float* d, const uint32_t* a, uint2 b) {
    asm volatile("mma.sync.aligned.m16n8k16.row.col.f32.bf16.bf16.f32 "
        "{%0,%1,%2,%3}, {%4,%5,%6,%7}, {%8,%9}, {%0,%1,%2,%3};"
        : "+f"(d[0]), "+f"(d[1]), "+f"(d[2]), "+f"(d[3])
        : "r"(a[0]), "r"(a[1]), "r"(a[2]), "r"(a[3]), "r"(b.x), "r"(b.y));
}

// =============== K1: neighbor GRU via mma.sync bf16x3 (HMMA) ===============
#define H_WHI  0                 // u32[24][4][32][2]  24576 B
#define H_WLO  24576             // u32 same           24576 B
#define H_XS   49152             // float2[8][128]      8192 B
#define H_WIH  57344             // float2[192]         1536 B
#define H_BIH  58880             // float[192]           768 B
#define H_BHH  59648             // float[192]           768 B
#define H_SMEM 60416
#define H_NTILE (NSEQ / 128)     // 1024

__global__ __launch_bounds__(256)
void k1_ngru(const float* __restrict__ traj, const float* __restrict__ Wih,
             const float* __restrict__ Whh, const float* __restrict__ bih,
             const float* __restrict__ bhh)
{
    extern __shared__ char sh[];
    uint32_t* WHI = (uint32_t*)(sh + H_WHI);
    uint32_t* WLO = (uint32_t*)(sh + H_WLO);
    float2*   XS2 = (float2*)(sh + H_XS);
    float2*   WIH2= (float2*)(sh + H_WIH);
    float*    BIH = (float*)(sh + H_BIH);
    float*    BHH = (float*)(sh + H_BHH);

    const int tid  = threadIdx.x;
    const int lane = tid & 31;
    const int w    = tid >> 5;
    const int g    = lane >> 2;
    const int tig  = lane & 3;

    for (int e = tid; e < 3072; e += 256) {
        int l = e & 31, jtkt = e >> 5;
        int kt = jtkt & 3, jt = jtkt >> 2;
        int j = 8 * jt + (l >> 2);
        #pragma unroll
        for (int r = 0; r < 2; ++r) {
            int k = 16 * kt + 2 * (l & 3) + 8 * r;
            float w0 = Whh[j * 64 + k], w1 = Whh[j * 64 + k + 1];
            uint32_t hi = pack_bf2(w0, w1);
            uint32_t lo = pack_bf2(w0 - bf_lo(hi), w1 - bf_hi(hi));
            WHI[e * 2 + r] = hi;
            WLO[e * 2 + r] = lo;
        }
    }
    if (tid < 192) {
        WIH2[tid] = ((const float2*)Wih)[tid];
        BIH[tid] = bih[tid];
        BHH[tid] = bhh[tid];
    }
    __syncthreads();

    const int sl = w * 16 + g;

    for (int tile = blockIdx.x; tile < H_NTILE; tile += gridDim.x) {
        __syncthreads();
        {
            int s_ = tid >> 1, q0 = (tid & 1) * 2;
            const float4* tp = (const float4*)(traj + (size_t)(tile * 128 + s_) * 16);
            float4 v0 = tp[q0], v1 = tp[q0 + 1];
            XS2[(2 * q0 + 0) * 128 + s_] = make_float2(v0.x, v0.y);
            XS2[(2 * q0 + 1) * 128 + s_] = make_float2(v0.z, v0.w);
            XS2[(2 * q0 + 2) * 128 + s_] = make_float2(v1.x, v1.y);
            XS2[(2 * q0 + 3) * 128 + s_] = make_float2(v1.z, v1.w);
        }
        __syncthreads();

        uint32_t Ahi[4][4], Alo[4][4], Nhi[4][4], Nlo[4][4];
        #pragma unroll
        for (int kt = 0; kt < 4; ++kt)
            #pragma unroll
            for (int r = 0; r < 4; ++r) { Ahi[kt][r] = 0u; Alo[kt][r] = 0u; }

        for (int t = 0; t < 8; ++t) {
            float2 xA = XS2[t * 128 + sl];
            float2 xB = XS2[t * 128 + sl + 8];
            #pragma unroll 2
            for (int jt = 0; jt < 8; ++jt) {
                float dr[4], dz[4], dn[4];
                {
                    float2 b2 = *(const float2*)&BHH[8 * jt + 2 * tig];
                    dr[0] = b2.x; dr[1] = b2.y; dr[2] = b2.x; dr[3] = b2.y;
                    b2 = *(const float2*)&BHH[64 + 8 * jt + 2 * tig];
                    dz[0] = b2.x; dz[1] = b2.y; dz[2] = b2.x; dz[3] = b2.y;
                    b2 = *(const float2*)&BHH[128 + 8 * jt + 2 * tig];
                    dn[0] = b2.x; dn[1] = b2.y; dn[2] = b2.x; dn[3] = b2.y;
                }
                if (t > 0) {
                    #pragma unroll
                    for (int kt = 0; kt < 4; ++kt) {
                        uint2 bh = *(const uint2*)&WHI[((jt * 4 + kt) * 32 + lane) * 2];
                        uint2 bl = *(const uint2*)&WLO[((jt * 4 + kt) * 32 + lane) * 2];
                        mma16816(dr, Ahi[kt], bh);
                        mma16816(dr, Ahi[kt], bl);
                        mma16816(dr, Alo[kt], bh);
                    }
                    #pragma unroll
                    for (int kt = 0; kt < 4; ++kt) {
                        uint2 bh = *(const uint2*)&WHI[(((jt + 8) * 4 + kt) * 32 + lane) * 2];
                        uint2 bl = *(const uint2*)&WLO[(((jt + 8) * 4 + kt) * 32 + lane) * 2];
                        mma16816(dz, Ahi[kt], bh);
                        mma16816(dz, Ahi[kt], bl);
                        mma16816(dz, Alo[kt], bh);
                    }
                    #pragma unroll
                    for (int kt = 0; kt < 4; ++kt) {
                        uint2 bh = *(const uint2*)&WHI[(((jt + 16) * 4 + kt) * 32 + lane) * 2];
                        uint2 bl = *(const uint2*)&WLO[(((jt + 16) * 4 + kt) * 32 + lane) * 2];
                        mma16816(dn, Ahi[kt], bh);
                        mma16816(dn, Ahi[kt], bl);
                        mma16816(dn, Alo[kt], bh);
                    }
                }
                float4 wr4 = *(const float4*)&WIH2[8 * jt + 2 * tig];
                float4 wz4 = *(const float4*)&WIH2[64 + 8 * jt + 2 * tig];
                float4 wn4 = *(const float4*)&WIH2[128 + 8 * jt + 2 * tig];
                float2 br2 = *(const float2*)&BIH[8 * jt + 2 * tig];
                float2 bz2 = *(const float2*)&BIH[64 + 8 * jt + 2 * tig];
                float2 bn2 = *(const float2*)&BIH[128 + 8 * jt + 2 * tig];
                const int kt = jt >> 1;
                #pragma unroll
                for (int rh = 0; rh < 2; ++rh) {
                    float x0 = rh ? xB.x : xA.x;
                    float x1 = rh ? xB.y : xA.y;
                    const int reg = (jt & 1) * 2 + rh;
                    uint32_t uh = Ahi[kt][reg], ul = Alo[kt][reg];
                    float hold0 = bf_lo(uh) + bf_lo(ul);
                    float hold1 = bf_hi(uh) + bf_hi(ul);
                    float hnew0, hnew1;
                    #pragma unroll
                    for (int c = 0; c < 2; ++c) {
                        float hr = dr[rh * 2 + c];
                        float hz = dz[rh * 2 + c];
                        float hn = dn[rh * 2 + c];
                        float wrx = c ? wr4.z : wr4.x, wry = c ? wr4.w : wr4.y;
                        float wzx = c ? wz4.z : wz4.x, wzy = c ? wz4.w : wz4.y;
                        float wnx = c ? wn4.z : wn4.x, wny = c ? wn4.w : wn4.y;
                        float xr = fmaf(x0, wrx, fmaf(x1, wry, c ? br2.y : br2.x));
                        float xz = fmaf(x0, wzx, fmaf(x1, wzy, c ? bz2.y : bz2.x));
                        float xn = fmaf(x0, wnx, fmaf(x1, wny, c ? bn2.y : bn2.x));
                        float r = sigmoid_fast(xr + hr);
                        float z = sigmoid_fast(xz + hz);
                        float n = tanh_fast(fmaf(r, hn, xn));
                        float hold = c ? hold1 : hold0;
                        float h = fmaf(z, hold - n, n);
                        if (c) hnew1 = h; else hnew0 = h;
                    }
                    if (t < 7) {
                        uint32_t nh = pack_bf2(hnew0, hnew1);
                        uint32_t nl = pack_bf2(hnew0 - bf_lo(nh), hnew1 - bf_hi(nh));
                        Nhi[kt][reg] = nh; Nlo[kt][reg] = nl;
                    } else {
                        int seq = tile * 128 + sl + 8 * rh;
                        *(float2*)&g_nf[(size_t)seq * 64 + 8 * jt + 2 * tig] =
                            make_float2(hnew0, hnew1);
                    }
                }
            }
            if (t < 7) {
                #pragma unroll
                for (int kt = 0; kt < 4; ++kt)
                    #pragma unroll
                    for (int r = 0; r < 4; ++r) {
                        Ahi[kt][r] = Nhi[kt][r];
                        Alo[kt][r] = Nlo[kt][r];
                    }
            }
        }
    }
}

// ============================ K2: target GRU ============================
#define K2_WT  0
#define K2_HP  (K2_WT + 128*385)
#define K2_H   (K2_HP + 3*384)
#define K2_X   (K2_H + 384)
#define K2_WIH (K2_X + 48)
#define K2_BIH (K2_WIH + 768)
#define K2_BHH (K2_BIH + 384)
#define K2_SMEM ((K2_BHH + 384) * 4)

__global__ __launch_bounds__(384)
void k2_tgru(const float* __restrict__ traj, const float* __restrict__ Wih,
             const float* __restrict__ Whh, const float* __restrict__ bih,
             const float* __restrict__ bhh)
{
    extern __shared__ float sm[];
    float *WT = sm + K2_WT, *HP = sm + K2_HP, *H = sm + K2_H, *X = sm + K2_X;
    float *WIH = sm + K2_WIH, *BIH = sm + K2_BIH, *BHH = sm + K2_BHH;
    const int tid = threadIdx.x;

    for (int idx = tid; idx < 384*128; idx += 384)
        WT[(idx & 127) * 385 + (idx >> 7)] = Whh[idx];
    for (int idx = tid; idx < 768; idx += 384) WIH[idx] = Wih[idx];
    BIH[tid] = bih[tid]; BHH[tid] = bhh[tid];
    __syncthreads();

    const int s = tid >> 7, i = tid & 127;

    for (int tile = blockIdx.x; tile < (BB + 2) / 3; tile += gridDim.x) {
        const int seq0 = tile * 3;
        __syncthreads();
        if (tid < 48) {
            int sq = seq0 + tid / 16;
            X[tid] = (sq < BB) ? traj[sq * 16 + (tid & 15)] : 0.0f;
        }
        H[tid] = 0.0f;
        __syncthreads();

        for (int t = 0; t < 8; ++t) {
            {
                float b = BHH[tid];
                float a0 = b, a1 = b, a2 = b;
                #pragma unroll
                for (int k = 0; k < 128; k += 4) {
                    float4 h0 = *reinterpret_cast<const float4*>(H + k);
                    float4 h1 = *reinterpret_cast<const float4*>(H + 128 + k);
                    float4 h2 = *reinterpret_cast<const float4*>(H + 256 + k);
                    float w0 = WT[(k  )*385+tid], w1 = WT[(k+1)*385+tid];
                    float w2 = WT[(k+2)*385+tid], w3 = WT[(k+3)*385+tid];
                    a0 = fmaf(w0,h0.x,fmaf(w1,h0.y,fmaf(w2,h0.z,fmaf(w3,h0.w,a0))));
                    a1 = fmaf(w0,h1.x,fmaf(w1,h1.y,fmaf(w2,h1.z,fmaf(w3,h1.w,a1))));
                    a2 = fmaf(w0,h2.x,fmaf(w1,h2.y,fmaf(w2,h2.z,fmaf(w3,h2.w,a2))));
                }
                HP[tid] = a0; HP[384 + tid] = a1; HP[768 + tid] = a2;
            }
            __syncthreads();
            {
                float x0 = X[s*16 + t*2], x1 = X[s*16 + t*2 + 1];
                float xr = fmaf(x0, WIH[2*i],        fmaf(x1, WIH[2*i+1],        BIH[i]));
                float xz = fmaf(x0, WIH[2*(128+i)],  fmaf(x1, WIH[2*(128+i)+1],  BIH[128+i]));
                float xn = fmaf(x0, WIH[2*(256+i)],  fmaf(x1, WIH[2*(256+i)+1],  BIH[256+i]));
                float r = sigmoid_fast(xr + HP[s*384 + i]);
                float z = sigmoid_fast(xz + HP[s*384 + 128 + i]);
                float n = tanh_fast(fmaf(r, HP[s*384 + 256 + i], xn));
                H[s*128 + i] = fmaf(z, H[s*128 + i] - n, n);
            }
            __syncthreads();
        }
        int sq = seq0 + s;
        if (sq < BB) g_tf[sq * 128 + i] = H[s*128 + i];
    }
}

// =================== K3: sector features + per-sector MLP ===================
#define K3_W1T  0
#define K3_W2T  (K3_W1T + 68*129)
#define K3_NF   (K3_W2T + 128*129)
#define K3_FEAT (K3_NF + 4096)
#define K3_H1   (K3_FEAT + 8*68)
#define K3_WSUM (K3_H1 + 1024)
#define K3_WV   (K3_WSUM + 8)
#define K3_DIST (K3_WV + 64)
#define K3_VAL  (K3_DIST + 64)
#define K3_V0   (K3_VAL + 64)
#define K3_V1   (K3_V0 + 64)
#define K3_SMEM ((K3_V1 + 64) * 4)

__global__ __launch_bounds__(512)
void k3_sector(const float* __restrict__ ttraj, const float* __restrict__ ntraj,
               const float* __restrict__ ang, const float* __restrict__ mask,
               const float* __restrict__ W1, const float* __restrict__ b1,
               const float* __restrict__ W2, const float* __restrict__ b2)
{
    extern __shared__ float smf[];
    __shared__ int SID[64];
    float *W1T = smf + K3_W1T, *W2T = smf + K3_W2T, *NF = smf + K3_NF;
    float *FEAT = smf + K3_FEAT, *H1 = smf + K3_H1, *WSUM = smf + K3_WSUM;
    float *WV = smf + K3_WV, *DIST = smf + K3_DIST, *VAL = smf + K3_VAL;
    float *V0 = smf + K3_V0, *V1 = smf + K3_V1;
    const int tid = threadIdx.x;

    for (int idx = tid; idx < 128*68; idx += 512)
        W1T[(idx % 68) * 129 + (idx / 68)] = W1[idx];
    for (int idx = tid; idx < 128*128; idx += 512)
        W2T[(idx & 127) * 129 + (idx >> 7)] = W2[idx];
    __syncthreads();

    const int s = tid >> 6, i = tid & 63;

    for (int b = blockIdx.x; b < BB; b += gridDim.x) {
        __syncthreads();
        for (int idx = tid; idx < 4096; idx += 512)
            NF[idx] = g_nf[b * 4096 + idx];
        if (tid < 64) {
            const float* base = ntraj + (size_t)(b * 64 + tid) * 16;
            float px = base[14], py = base[15];
            float dx = px - ttraj[b*16 + 14], dy = py - ttraj[b*16 + 15];
            float d = sqrtf(dx*dx + dy*dy);
            DIST[tid] = d;
            V0[tid] = px - base[12];
            V1[tid] = py - base[13];
            int sid = (int)(ang[b*64 + tid] * 1.27323954473516f);
            SID[tid] = min(max(sid, 0), 7);
            float vf = (mask[b*64 + tid] > 0.0f) ? 1.0f : 0.0f;
            VAL[tid] = vf;
            WV[tid] = __expf(-d * 0.1f) * vf;
        }
        __syncthreads();
        if (tid < 8) {
            float cnt = 0.f, dsum = 0.f, v0 = 0.f, v1 = 0.f, ws = 0.f;
            for (int n = 0; n < 64; ++n) {
                bool in = (SID[n] == tid);
                float m = in ? VAL[n] : 0.0f;
                cnt += m; dsum += m * DIST[n]; v0 += m * V0[n]; v1 += m * V1[n];
                ws += in ? WV[n] : 0.0f;
            }
            float safe = fmaxf(cnt, 1.0f);
            bool ne = cnt > 0.0f;
            FEAT[tid*68 + 0] = cnt;
            FEAT[tid*68 + 1] = ne ? dsum / safe : 0.0f;
            FEAT[tid*68 + 2] = ne ? v0 / safe : 0.0f;
            FEAT[tid*68 + 3] = ne ? v1 / safe : 0.0f;
            WSUM[tid] = ws + 1e-8f;
        }
        __syncthreads();
        {
            float acc = 0.0f;
            for (int n = 0; n < 64; ++n) {
                float wm = (SID[n] == s) ? WV[n] : 0.0f;
                acc = fmaf(wm, NF[n*64 + i], acc);
            }
            FEAT[s*68 + 4 + i] = acc / WSUM[s];
        }
        __syncthreads();
        for (int o = tid; o < 1024; o += 512) {
            int os = o >> 7, oj = o & 127;
            float acc = b1[oj];
            #pragma unroll
            for (int k = 0; k < 68; ++k)
                acc = fmaf(FEAT[os*68 + k], W1T[k*129 + oj], acc);
            H1[os*128 + oj] = fmaxf(acc, 0.0f);
        }
        __syncthreads();
        for (int o = tid; o < 1024; o += 512) {
            int os = o >> 7, oj = o & 127;
            float acc = b2[oj];
            #pragma unroll
            for (int k = 0; k < 128; ++k)
                acc = fmaf(H1[os*128 + k], W2T[k*129 + oj], acc);
            g_enc[b * 1024 + o] = fmaxf(acc, 0.0f);
        }
    }
}

// =================== K5: f1 = relu([tf,enc] @ Wf1.T + bf1) ===================
// M-tile 8, grid 256 (reverted to measured-best config).
#define K5_PAD 12
#define K5_SMEM ((32*257 + 32*K5_PAD) * 4)

__global__ __launch_bounds__(256)
void k5_f1(const float* __restrict__ Wf1, const float* __restrict__ bf1)
{
    extern __shared__ float k5s[];
    float* Wsh = k5s;
    float* Ash = k5s + 32 * 257;

    const int tid = threadIdx.x;
    const int m0 = blockIdx.x * 8;
    const int jb = tid >> 5, kk = tid & 31;

    float acc[8];
    float bv = bf1[tid];
    #pragma unroll
    for (int r = 0; r < 8; ++r) acc[r] = bv;

    float wreg[32];
    float areg;

    #pragma unroll
    for (int rr = 0; rr < 32; ++rr)
        wreg[rr] = Wf1[(jb + rr * 8) * 1152 + kk];
    areg = g_tf[(m0 + jb) * 128 + kk];

    for (int c = 0; c < 36; ++c) {
        __syncthreads();
        #pragma unroll
        for (int rr = 0; rr < 32; ++rr)
            Wsh[kk * 257 + jb + rr * 8] = wreg[rr];
        Ash[kk * K5_PAD + jb] = areg;
        __syncthreads();
        if (c < 35) {
            const int k0 = (c + 1) * 32;
            #pragma unroll
            for (int rr = 0; rr < 32; ++rr)
                wreg[rr] = Wf1[(jb + rr * 8) * 1152 + k0 + kk];
            int gk = k0 + kk;
            areg = (gk < 128) ? g_tf[(m0 + jb) * 128 + gk]
                              : g_enc[(m0 + jb) * 1024 + gk - 128];
        }
        #pragma unroll
        for (int q = 0; q < 32; ++q) {
            float w = Wsh[q * 257 + tid];
            float4 a0 = *reinterpret_cast<const float4*>(&Ash[q * K5_PAD]);
            float4 a1 = *reinterpret_cast<const float4*>(&Ash[q * K5_PAD + 4]);
            acc[0]=fmaf(w,a0.x,acc[0]); acc[1]=fmaf(w,a0.y,acc[1]);
            acc[2]=fmaf(w,a0.z,acc[2]); acc[3]=fmaf(w,a0.w,acc[3]);
            acc[4]=fmaf(w,a1.x,acc[4]); acc[5]=fmaf(w,a1.y,acc[5]);
            acc[6]=fmaf(w,a1.z,acc[6]); acc[7]=fmaf(w,a1.w,acc[7]);
        }
    }
    #pragma unroll
    for (int r = 0; r < 8; ++r)
        g_f1[(m0 + r) * 256 + tid] = fmaxf(acc[r], 0.0f);
}

// =================== K6: f2, f3, LayerNorm ===================
#define K6_W2T 0
#define K6_W3T (K6_W2T + 256*129)
#define K6_F1  (K6_W3T + 128*65)
#define K6_F2  (K6_F1 + 16*257)
#define K6_F3  (K6_F2 + 16*129)
#define K6_MU  (K6_F3 + 1024)
#define K6_RS  (K6_MU + 16)
#define K6_SMEM ((K6_RS + 16) * 4)

__global__ __launch_bounds__(128)
void k6_final(const float* __restrict__ Wf2, const float* __restrict__ bf2,
              const float* __restrict__ Wf3, const float* __restrict__ bf3,
              const float* __restrict__ ln_g, const float* __restrict__ ln_b,
              float* __restrict__ out)
{
    extern __shared__ float smf[];
    float *W2T = smf + K6_W2T, *W3T = smf + K6_W3T, *F1 = smf + K6_F1;
    float *F2 = smf + K6_F2, *F3 = smf + K6_F3, *MU = smf + K6_MU, *RS = smf + K6_RS;
    const int tid = threadIdx.x;
    const int m0 = blockIdx.x * 16;

    for (int idx = tid; idx < 128*256; idx += 128)
        W2T[(idx & 255) * 129 + (idx >> 8)] = Wf2[idx];
    for (int idx = tid; idx < 64*128; idx += 128)
        W3T[(idx & 127) * 65 + (idx >> 7)] = Wf3[idx];
    for (int idx = tid; idx < 16*256; idx += 128)
        F1[(idx >> 8) * 257 + (idx & 255)] = g_f1[m0 * 256 + idx];
    __syncthreads();

    {
        float acc[16];
        float bv = bf2[tid];
        #pragma unroll
        for (int r = 0; r < 16; ++r) acc[r] = bv;
        for (int k = 0; k < 256; ++k) {
            float w = W2T[k * 129 + tid];
            #pragma unroll
            for (int r = 0; r < 16; ++r)
                acc[r] = fmaf(F1[r * 257 + k], w, acc[r]);
        }
        #pragma unroll
        for (int r = 0; r < 16; ++r)
            F2[r * 129 + tid] = fmaxf(acc[r], 0.0f);
    }
    __syncthreads();
    for (int o = tid; o < 1024; o += 128) {
        int r = o >> 6, j = o & 63;
        float acc = bf3[j];
        #pragma unroll
        for (int k = 0; k < 128; ++k)
            acc = fmaf(F2[r * 129 + k], W3T[k * 65 + j], acc);
        F3[o] = fmaxf(acc, 0.0f);
    }
    __syncthreads();
    if (tid < 16) {
        float s0 = 0.f;
        #pragma unroll
        for (int j = 0; j < 64; ++j) s0 += F3[tid*64 + j];
        float mu = s0 * (1.0f / 64.0f);
        float v = 0.f;
        #pragma unroll
        for (int j = 0; j < 64; ++j) { float dd = F3[tid*64 + j] - mu; v = fmaf(dd, dd, v); }
        MU[tid] = mu;
        RS[tid] = rsqrtf(v * (1.0f / 64.0f) + 1e-5f);
    }
    __syncthreads();
    for (int o = tid; o < 1024; o += 128) {
        int r = o >> 6, j = o & 63;
        out[(m0 + r) * 64 + j] = (F3[o] - MU[r]) * RS[r] * ln_g[j] + ln_b[j];
    }
}

// =============================== launch ===============================
extern "C" void kernel_launch(void* const* d_in, const int* in_sizes, int n_in,
                              void* d_out, int out_size)
{
    const float* ttraj = (const float*)d_in[0];
    const float* ntraj = (const float*)d_in[1];
    const float* ang   = (const float*)d_in[2];
    const float* mask  = (const float*)d_in[3];
    const float* Wih_t = (const float*)d_in[4];
    const float* Whh_t = (const float*)d_in[5];
    const float* bih_t = (const float*)d_in[6];
    const float* bhh_t = (const float*)d_in[7];
    const float* Wih_n = (const float*)d_in[8];
    const float* Whh_n = (const float*)d_in[9];
    const float* bih_n = (const float*)d_in[10];
    const float* bhh_n = (const float*)d_in[11];
    const float* W1  = (const float*)d_in[12];
    const float* b1  = (const float*)d_in[13];
    const float* W2  = (const float*)d_in[14];
    const float* b2  = (const float*)d_in[15];
    const float* Wf1 = (const float*)d_in[16];
    const float* bf1 = (const float*)d_in[17];
    const float* Wf2 = (const float*)d_in[18];
    const float* bf2 = (const float*)d_in[19];
    const float* Wf3 = (const float*)d_in[20];
    const float* bf3 = (const float*)d_in[21];
    const float* ln_g = (const float*)d_in[22];
    const float* ln_b = (const float*)d_in[23];
    float* out = (float*)d_out;

    cudaFuncSetAttribute(k1_ngru,   cudaFuncAttributeMaxDynamicSharedMemorySize, H_SMEM);
    cudaFuncSetAttribute(k2_tgru,   cudaFuncAttributeMaxDynamicSharedMemorySize, K2_SMEM);
    cudaFuncSetAttribute(k3_sector, cudaFuncAttributeMaxDynamicSharedMemorySize, K3_SMEM);
    cudaFuncSetAttribute(k5_f1,     cudaFuncAttributeMaxDynamicSharedMemorySize, K5_SMEM);
    cudaFuncSetAttribute(k6_final,  cudaFuncAttributeMaxDynamicSharedMemorySize, K6_SMEM);

    k1_ngru<<<296, 256, H_SMEM>>>(ntraj, Wih_n, Whh_n, bih_n, bhh_n);
    k2_tgru<<<148, 384, K2_SMEM>>>(ttraj, Wih_t, Whh_t, bih_t, bhh_t);
    k3_sector<<<296, 512, K3_SMEM>>>(ttraj, ntraj, ang, mask, W1, b1, W2, b2);
    k5_f1<<<256, 256, K5_SMEM>>>(Wf1, bf1);
    k6_final<<<128, 128, K6_SMEM>>>(Wf2, bf2, Wf3, bf3, ln_g, ln_b, out);
}

// round 16
// speedup vs baseline: 1.2117x; 1.0821x over previous
#include <cuda_runtime.h>
#include <stdint.h>
#include <math.h>

#define BB   2048
#define NNB  64
#define HH   128
#define HN   64
#define NSEQ (BB*NNB)

__device__ float g_nf[NSEQ * HN];        // neighbor GRU features
__device__ float g_tf[BB * HH];          // target GRU features
__device__ float g_enc[BB * 8 * HH];     // per-sector MLP output
__device__ float g_f1[BB * 256];         // first final-MLP layer

// fast activations: hardware tanh (MUFU.TANH), sigmoid via tanh identity
__device__ __forceinline__ float tanh_fast(float x) {
    float y; asm("tanh.approx.f32 %0, %1;" : "=f"(y) : "f"(x)); return y;
}
__device__ __forceinline__ float sigmoid_fast(float x) {
    return fmaf(0.5f, tanh_fast(0.5f * x), 0.5f);
}
__device__ __forceinline__ uint32_t pack_bf2(float lo, float hi) {
    uint32_t r;
    asm("cvt.rn.bf16x2.f32 %0, %1, %2;" : "=r"(r) : "f"(hi), "f"(lo));
    return r;
}
__device__ __forceinline__ float bf_lo(uint32_t u) { return __uint_as_float(u << 16); }
__device__ __forceinline__ float bf_hi(uint32_t u) { return __uint_as_float(u & 0xFFFF0000u); }

__device__ __forceinline__ void mma16816(float* d, const uint32_t* a, uint2 b) {
    asm volatile("mma.sync.aligned.m16n8k16.row.col.f32.bf16.bf16.f32 "
        "{%0,%1,%2,%3}, {%4,%5,%6,%7}, {%8,%9}, {%0,%1,%2,%3};"
        : "+f"(d[0]), "+f"(d[1]), "+f"(d[2]), "+f"(d[3])
        : "r"(a[0]), "r"(a[1]), "r"(a[2]), "r"(a[3]), "r"(b.x), "r"(b.y));
}

// =============== K1: neighbor GRU via mma.sync, asymmetric bf16 precision ===============
// r,z (sigmoid) gates: single bf16 product. n (tanh) gate: bf16x3.
#define H_WHI  0                 // u32[24][4][32][2]  24576 B
#define H_WLO  24576             // u32 same           24576 B
#define H_XS   49152             // float2[8][128]      8192 B
#define H_WIH  57344             // float2[192]         1536 B
#define H_BIH  58880             // float[192]           768 B
#define H_BHH  59648             // float[192]           768 B
#define H_SMEM 60416
#define H_NTILE (NSEQ / 128)     // 1024

__global__ __launch_bounds__(256)
void k1_ngru(const float* __restrict__ traj, const float* __restrict__ Wih,
             const float* __restrict__ Whh, const float* __restrict__ bih,
             const float* __restrict__ bhh)
{
    extern __shared__ char sh[];
    uint32_t* WHI = (uint32_t*)(sh + H_WHI);
    uint32_t* WLO = (uint32_t*)(sh + H_WLO);
    float2*   XS2 = (float2*)(sh + H_XS);
    float2*   WIH2= (float2*)(sh + H_WIH);
    float*    BIH = (float*)(sh + H_BIH);
    float*    BHH = (float*)(sh + H_BHH);

    const int tid  = threadIdx.x;
    const int lane = tid & 31;
    const int w    = tid >> 5;
    const int g    = lane >> 2;
    const int tig  = lane & 3;

    for (int e = tid; e < 3072; e += 256) {
        int l = e & 31, jtkt = e >> 5;
        int kt = jtkt & 3, jt = jtkt >> 2;
        int j = 8 * jt + (l >> 2);
        #pragma unroll
        for (int r = 0; r < 2; ++r) {
            int k = 16 * kt + 2 * (l & 3) + 8 * r;
            float w0 = Whh[j * 64 + k], w1 = Whh[j * 64 + k + 1];
            uint32_t hi = pack_bf2(w0, w1);
            uint32_t lo = pack_bf2(w0 - bf_lo(hi), w1 - bf_hi(hi));
            WHI[e * 2 + r] = hi;
            WLO[e * 2 + r] = lo;
        }
    }
    if (tid < 192) {
        WIH2[tid] = ((const float2*)Wih)[tid];
        BIH[tid] = bih[tid];
        BHH[tid] = bhh[tid];
    }
    __syncthreads();

    const int sl = w * 16 + g;

    for (int tile = blockIdx.x; tile < H_NTILE; tile += gridDim.x) {
        __syncthreads();
        {
            int s_ = tid >> 1, q0 = (tid & 1) * 2;
            const float4* tp = (const float4*)(traj + (size_t)(tile * 128 + s_) * 16);
            float4 v0 = tp[q0], v1 = tp[q0 + 1];
            XS2[(2 * q0 + 0) * 128 + s_] = make_float2(v0.x, v0.y);
            XS2[(2 * q0 + 1) * 128 + s_] = make_float2(v0.z, v0.w);
            XS2[(2 * q0 + 2) * 128 + s_] = make_float2(v1.x, v1.y);
            XS2[(2 * q0 + 3) * 128 + s_] = make_float2(v1.z, v1.w);
        }
        __syncthreads();

        uint32_t Ahi[4][4], Alo[4][4], Nhi[4][4], Nlo[4][4];
        #pragma unroll
        for (int kt = 0; kt < 4; ++kt)
            #pragma unroll
            for (int r = 0; r < 4; ++r) { Ahi[kt][r] = 0u; Alo[kt][r] = 0u; }

        for (int t = 0; t < 8; ++t) {
            float2 xA = XS2[t * 128 + sl];
            float2 xB = XS2[t * 128 + sl + 8];
            #pragma unroll 2
            for (int jt = 0; jt < 8; ++jt) {
                float dr[4], dz[4], dn[4];
                {
                    float2 b2 = *(const float2*)&BHH[8 * jt + 2 * tig];
                    dr[0] = b2.x; dr[1] = b2.y; dr[2] = b2.x; dr[3] = b2.y;
                    b2 = *(const float2*)&BHH[64 + 8 * jt + 2 * tig];
                    dz[0] = b2.x; dz[1] = b2.y; dz[2] = b2.x; dz[3] = b2.y;
                    b2 = *(const float2*)&BHH[128 + 8 * jt + 2 * tig];
                    dn[0] = b2.x; dn[1] = b2.y; dn[2] = b2.x; dn[3] = b2.y;
                }
                if (t > 0) {
                    // r gate: single bf16 product (sigmoid tolerates ~2^-9)
                    #pragma unroll
                    for (int kt = 0; kt < 4; ++kt) {
                        uint2 bh = *(const uint2*)&WHI[((jt * 4 + kt) * 32 + lane) * 2];
                        mma16816(dr, Ahi[kt], bh);
                    }
                    // z gate: single bf16 product
                    #pragma unroll
                    for (int kt = 0; kt < 4; ++kt) {
                        uint2 bh = *(const uint2*)&WHI[(((jt + 8) * 4 + kt) * 32 + lane) * 2];
                        mma16816(dz, Ahi[kt], bh);
                    }
                    // n gate: full bf16x3 (feeds tanh and h directly)
                    #pragma unroll
                    for (int kt = 0; kt < 4; ++kt) {
                        uint2 bh = *(const uint2*)&WHI[(((jt + 16) * 4 + kt) * 32 + lane) * 2];
                        uint2 bl = *(const uint2*)&WLO[(((jt + 16) * 4 + kt) * 32 + lane) * 2];
                        mma16816(dn, Ahi[kt], bh);
                        mma16816(dn, Ahi[kt], bl);
                        mma16816(dn, Alo[kt], bh);
                    }
                }
                float4 wr4 = *(const float4*)&WIH2[8 * jt + 2 * tig];
                float4 wz4 = *(const float4*)&WIH2[64 + 8 * jt + 2 * tig];
                float4 wn4 = *(const float4*)&WIH2[128 + 8 * jt + 2 * tig];
                float2 br2 = *(const float2*)&BIH[8 * jt + 2 * tig];
                float2 bz2 = *(const float2*)&BIH[64 + 8 * jt + 2 * tig];
                float2 bn2 = *(const float2*)&BIH[128 + 8 * jt + 2 * tig];
                const int kt = jt >> 1;
                #pragma unroll
                for (int rh = 0; rh < 2; ++rh) {
                    float x0 = rh ? xB.x : xA.x;
                    float x1 = rh ? xB.y : xA.y;
                    const int reg = (jt & 1) * 2 + rh;
                    uint32_t uh = Ahi[kt][reg], ul = Alo[kt][reg];
                    float hold0 = bf_lo(uh) + bf_lo(ul);
                    float hold1 = bf_hi(uh) + bf_hi(ul);
                    float hnew0, hnew1;
                    #pragma unroll
                    for (int c = 0; c < 2; ++c) {
                        float hr = dr[rh * 2 + c];
                        float hz = dz[rh * 2 + c];
                        float hn = dn[rh * 2 + c];
                        float wrx = c ? wr4.z : wr4.x, wry = c ? wr4.w : wr4.y;
                        float wzx = c ? wz4.z : wz4.x, wzy = c ? wz4.w : wz4.y;
                        float wnx = c ? wn4.z : wn4.x, wny = c ? wn4.w : wn4.y;
                        float xr = fmaf(x0, wrx, fmaf(x1, wry, c ? br2.y : br2.x));
                        float xz = fmaf(x0, wzx, fmaf(x1, wzy, c ? bz2.y : bz2.x));
                        float xn = fmaf(x0, wnx, fmaf(x1, wny, c ? bn2.y : bn2.x));
                        float r = sigmoid_fast(xr + hr);
                        float z = sigmoid_fast(xz + hz);
                        float n = tanh_fast(fmaf(r, hn, xn));
                        float hold = c ? hold1 : hold0;
                        float h = fmaf(z, hold - n, n);
                        if (c) hnew1 = h; else hnew0 = h;
                    }
                    if (t < 7) {
                        uint32_t nh = pack_bf2(hnew0, hnew1);
                        uint32_t nl = pack_bf2(hnew0 - bf_lo(nh), hnew1 - bf_hi(nh));
                        Nhi[kt][reg] = nh; Nlo[kt][reg] = nl;
                    } else {
                        int seq = tile * 128 + sl + 8 * rh;
                        *(float2*)&g_nf[(size_t)seq * 64 + 8 * jt + 2 * tig] =
                            make_float2(hnew0, hnew1);
                    }
                }
            }
            if (t < 7) {
                #pragma unroll
                for (int kt = 0; kt < 4; ++kt)
                    #pragma unroll
                    for (int r = 0; r < 4; ++r) {
                        Ahi[kt][r] = Nhi[kt][r];
                        Alo[kt][r] = Nlo[kt][r];
                    }
            }
        }
    }
}

// ============================ K2: target GRU ============================
#define K2_WT  0
#define K2_HP  (K2_WT + 128*385)
#define K2_H   (K2_HP + 3*384)
#define K2_X   (K2_H + 384)
#define K2_WIH (K2_X + 48)
#define K2_BIH (K2_WIH + 768)
#define K2_BHH (K2_BIH + 384)
#define K2_SMEM ((K2_BHH + 384) * 4)

__global__ __launch_bounds__(384)
void k2_tgru(const float* __restrict__ traj, const float* __restrict__ Wih,
             const float* __restrict__ Whh, const float* __restrict__ bih,
             const float* __restrict__ bhh)
{
    extern __shared__ float sm[];
    float *WT = sm + K2_WT, *HP = sm + K2_HP, *H = sm + K2_H, *X = sm + K2_X;
    float *WIH = sm + K2_WIH, *BIH = sm + K2_BIH, *BHH = sm + K2_BHH;
    const int tid = threadIdx.x;

    for (int idx = tid; idx < 384*128; idx += 384)
        WT[(idx & 127) * 385 + (idx >> 7)] = Whh[idx];
    for (int idx = tid; idx < 768; idx += 384) WIH[idx] = Wih[idx];
    BIH[tid] = bih[tid]; BHH[tid] = bhh[tid];
    __syncthreads();

    const int s = tid >> 7, i = tid & 127;

    for (int tile = blockIdx.x; tile < (BB + 2) / 3; tile += gridDim.x) {
        const int seq0 = tile * 3;
        __syncthreads();
        if (tid < 48) {
            int sq = seq0 + tid / 16;
            X[tid] = (sq < BB) ? traj[sq * 16 + (tid & 15)] : 0.0f;
        }
        H[tid] = 0.0f;
        __syncthreads();

        for (int t = 0; t < 8; ++t) {
            {
                float b = BHH[tid];
                float a0 = b, a1 = b, a2 = b;
                #pragma unroll
                for (int k = 0; k < 128; k += 4) {
                    float4 h0 = *reinterpret_cast<const float4*>(H + k);
                    float4 h1 = *reinterpret_cast<const float4*>(H + 128 + k);
                    float4 h2 = *reinterpret_cast<const float4*>(H + 256 + k);
                    float w0 = WT[(k  )*385+tid], w1 = WT[(k+1)*385+tid];
                    float w2 = WT[(k+2)*385+tid], w3 = WT[(k+3)*385+tid];
                    a0 = fmaf(w0,h0.x,fmaf(w1,h0.y,fmaf(w2,h0.z,fmaf(w3,h0.w,a0))));
                    a1 = fmaf(w0,h1.x,fmaf(w1,h1.y,fmaf(w2,h1.z,fmaf(w3,h1.w,a1))));
                    a2 = fmaf(w0,h2.x,fmaf(w1,h2.y,fmaf(w2,h2.z,fmaf(w3,h2.w,a2))));
                }
                HP[tid] = a0; HP[384 + tid] = a1; HP[768 + tid] = a2;
            }
            __syncthreads();
            {
                float x0 = X[s*16 + t*2], x1 = X[s*16 + t*2 + 1];
                float xr = fmaf(x0, WIH[2*i],        fmaf(x1, WIH[2*i+1],        BIH[i]));
                float xz = fmaf(x0, WIH[2*(128+i)],  fmaf(x1, WIH[2*(128+i)+1],  BIH[128+i]));
                float xn = fmaf(x0, WIH[2*(256+i)],  fmaf(x1, WIH[2*(256+i)+1],  BIH[256+i]));
                float r = sigmoid_fast(xr + HP[s*384 + i]);
                float z = sigmoid_fast(xz + HP[s*384 + 128 + i]);
                float n = tanh_fast(fmaf(r, HP[s*384 + 256 + i], xn));
                H[s*128 + i] = fmaf(z, H[s*128 + i] - n, n);
            }
            __syncthreads();
        }
        int sq = seq0 + s;
        if (sq < BB) g_tf[sq * 128 + i] = H[s*128 + i];
    }
}

// =================== K3: sector features + per-sector MLP ===================
#define K3_W1T  0
#define K3_W2T  (K3_W1T + 68*129)
#define K3_NF   (K3_W2T + 128*129)
#define K3_FEAT (K3_NF + 4096)
#define K3_H1   (K3_FEAT + 8*68)
#define K3_WSUM (K3_H1 + 1024)
#define K3_WV   (K3_WSUM + 8)
#define K3_DIST (K3_WV + 64)
#define K3_VAL  (K3_DIST + 64)
#define K3_V0   (K3_VAL + 64)
#define K3_V1   (K3_V0 + 64)
#define K3_SMEM ((K3_V1 + 64) * 4)

__global__ __launch_bounds__(512)
void k3_sector(const float* __restrict__ ttraj, const float* __restrict__ ntraj,
               const float* __restrict__ ang, const float* __restrict__ mask,
               const float* __restrict__ W1, const float* __restrict__ b1,
               const float* __restrict__ W2, const float* __restrict__ b2)
{
    extern __shared__ float smf[];
    __shared__ int SID[64];
    float *W1T = smf + K3_W1T, *W2T = smf + K3_W2T, *NF = smf + K3_NF;
    float *FEAT = smf + K3_FEAT, *H1 = smf + K3_H1, *WSUM = smf + K3_WSUM;
    float *WV = smf + K3_WV, *DIST = smf + K3_DIST, *VAL = smf + K3_VAL;
    float *V0 = smf + K3_V0, *V1 = smf + K3_V1;
    const int tid = threadIdx.x;

    for (int idx = tid; idx < 128*68; idx += 512)
        W1T[(idx % 68) * 129 + (idx / 68)] = W1[idx];
    for (int idx = tid; idx < 128*128; idx += 512)
        W2T[(idx & 127) * 129 + (idx >> 7)] = W2[idx];
    __syncthreads();

    const int s = tid >> 6, i = tid & 63;

    for (int b = blockIdx.x; b < BB; b += gridDim.x) {
        __syncthreads();
        for (int idx = tid; idx < 4096; idx += 512)
            NF[idx] = g_nf[b * 4096 + idx];
        if (tid < 64) {
            const float* base = ntraj + (size_t)(b * 64 + tid) * 16;
            float px = base[14], py = base[15];
            float dx = px - ttraj[b*16 + 14], dy = py - ttraj[b*16 + 15];
            float d = sqrtf(dx*dx + dy*dy);
            DIST[tid] = d;
            V0[tid] = px - base[12];
            V1[tid] = py - base[13];
            int sid = (int)(ang[b*64 + tid] * 1.27323954473516f);
            SID[tid] = min(max(sid, 0), 7);
            float vf = (mask[b*64 + tid] > 0.0f) ? 1.0f : 0.0f;
            VAL[tid] = vf;
            WV[tid] = __expf(-d * 0.1f) * vf;
        }
        __syncthreads();
        if (tid < 8) {
            float cnt = 0.f, dsum = 0.f, v0 = 0.f, v1 = 0.f, ws = 0.f;
            for (int n = 0; n < 64; ++n) {
                bool in = (SID[n] == tid);
                float m = in ? VAL[n] : 0.0f;
                cnt += m; dsum += m * DIST[n]; v0 += m * V0[n]; v1 += m * V1[n];
                ws += in ? WV[n] : 0.0f;
            }
            float safe = fmaxf(cnt, 1.0f);
            bool ne = cnt > 0.0f;
            FEAT[tid*68 + 0] = cnt;
            FEAT[tid*68 + 1] = ne ? dsum / safe : 0.0f;
            FEAT[tid*68 + 2] = ne ? v0 / safe : 0.0f;
            FEAT[tid*68 + 3] = ne ? v1 / safe : 0.0f;
            WSUM[tid] = ws + 1e-8f;
        }
        __syncthreads();
        {
            float acc = 0.0f;
            for (int n = 0; n < 64; ++n) {
                float wm = (SID[n] == s) ? WV[n] : 0.0f;
                acc = fmaf(wm, NF[n*64 + i], acc);
            }
            FEAT[s*68 + 4 + i] = acc / WSUM[s];
        }
        __syncthreads();
        for (int o = tid; o < 1024; o += 512) {
            int os = o >> 7, oj = o & 127;
            float acc = b1[oj];
            #pragma unroll
            for (int k = 0; k < 68; ++k)
                acc = fmaf(FEAT[os*68 + k], W1T[k*129 + oj], acc);
            H1[os*128 + oj] = fmaxf(acc, 0.0f);
        }
        __syncthreads();
        for (int o = tid; o < 1024; o += 512) {
            int os = o >> 7, oj = o & 127;
            float acc = b2[oj];
            #pragma unroll
            for (int k = 0; k < 128; ++k)
                acc = fmaf(H1[os*128 + k], W2T[k*129 + oj], acc);
            g_enc[b * 1024 + o] = fmaxf(acc, 0.0f);
        }
    }
}

// =================== K5: f1 = relu([tf,enc] @ Wf1.T + bf1) ===================
#define K5_PAD 12
#define K5_SMEM ((32*257 + 32*K5_PAD) * 4)

__global__ __launch_bounds__(256)
void k5_f1(const float* __restrict__ Wf1, const float* __restrict__ bf1)
{
    extern __shared__ float k5s[];
    float* Wsh = k5s;
    float* Ash = k5s + 32 * 257;

    const int tid = threadIdx.x;
    const int m0 = blockIdx.x * 8;
    const int jb = tid >> 5, kk = tid & 31;

    float acc[8];
    float bv = bf1[tid];
    #pragma unroll
    for (int r = 0; r < 8; ++r) acc[r] = bv;

    float wreg[32];
    float areg;

    #pragma unroll
    for (int rr = 0; rr < 32; ++rr)
        wreg[rr] = Wf1[(jb + rr * 8) * 1152 + kk];
    areg = g_tf[(m0 + jb) * 128 + kk];

    for (int c = 0; c < 36; ++c) {
        __syncthreads();
        #pragma unroll
        for (int rr = 0; rr < 32; ++rr)
            Wsh[kk * 257 + jb + rr * 8] = wreg[rr];
        Ash[kk * K5_PAD + jb] = areg;
        __syncthreads();
        if (c < 35) {
            const int k0 = (c + 1) * 32;
            #pragma unroll
            for (int rr = 0; rr < 32; ++rr)
                wreg[rr] = Wf1[(jb + rr * 8) * 1152 + k0 + kk];
            int gk = k0 + kk;
            areg = (gk < 128) ? g_tf[(m0 + jb) * 128 + gk]
                              : g_enc[(m0 + jb) * 1024 + gk - 128];
        }
        #pragma unroll
        for (int q = 0; q < 32; ++q) {
            float w = Wsh[q * 257 + tid];
            float4 a0 = *reinterpret_cast<const float4*>(&Ash[q * K5_PAD]);
            float4 a1 = *reinterpret_cast<const float4*>(&Ash[q * K5_PAD + 4]);
            acc[0]=fmaf(w,a0.x,acc[0]); acc[1]=fmaf(w,a0.y,acc[1]);
            acc[2]=fmaf(w,a0.z,acc[2]); acc[3]=fmaf(w,a0.w,acc[3]);
            acc[4]=fmaf(w,a1.x,acc[4]); acc[5]=fmaf(w,a1.y,acc[5]);
            acc[6]=fmaf(w,a1.z,acc[6]); acc[7]=fmaf(w,a1.w,acc[7]);
        }
    }
    #pragma unroll
    for (int r = 0; r < 8; ++r)
        g_f1[(m0 + r) * 256 + tid] = fmaxf(acc[r], 0.0f);
}

// =================== K6: f2, f3, LayerNorm ===================
#define K6_W2T 0
#define K6_W3T (K6_W2T + 256*129)
#define K6_F1  (K6_W3T + 128*65)
#define K6_F2  (K6_F1 + 16*257)
#define K6_F3  (K6_F2 + 16*129)
#define K6_MU  (K6_F3 + 1024)
#define K6_RS  (K6_MU + 16)
#define K6_SMEM ((K6_RS + 16) * 4)

__global__ __launch_bounds__(128)
void k6_final(const float* __restrict__ Wf2, const float* __restrict__ bf2,
              const float* __restrict__ Wf3, const float* __restrict__ bf3,
              const float* __restrict__ ln_g, const float* __restrict__ ln_b,
              float* __restrict__ out)
{
    extern __shared__ float smf[];
    float *W2T = smf + K6_W2T, *W3T = smf + K6_W3T, *F1 = smf + K6_F1;
    float *F2 = smf + K6_F2, *F3 = smf + K6_F3, *MU = smf + K6_MU, *RS = smf + K6_RS;
    const int tid = threadIdx.x;
    const int m0 = blockIdx.x * 16;

    for (int idx = tid; idx < 128*256; idx += 128)
        W2T[(idx & 255) * 129 + (idx >> 8)] = Wf2[idx];
    for (int idx = tid; idx < 64*128; idx += 128)
        W3T[(idx & 127) * 65 + (idx >> 7)] = Wf3[idx];
    for (int idx = tid; idx < 16*256; idx += 128)
        F1[(idx >> 8) * 257 + (idx & 255)] = g_f1[m0 * 256 + idx];
    __syncthreads();

    {
        float acc[16];
        float bv = bf2[tid];
        #pragma unroll
        for (int r = 0; r < 16; ++r) acc[r] = bv;
        for (int k = 0; k < 256; ++k) {
            float w = W2T[k * 129 + tid];
            #pragma unroll
            for (int r = 0; r < 16; ++r)
                acc[r] = fmaf(F1[r * 257 + k], w, acc[r]);
        }
        #pragma unroll
        for (int r = 0; r < 16; ++r)
            F2[r * 129 + tid] = fmaxf(acc[r], 0.0f);
    }
    __syncthreads();
    for (int o = tid; o < 1024; o += 128) {
        int r = o >> 6, j = o & 63;
        float acc = bf3[j];
        #pragma unroll
        for (int k = 0; k < 128; ++k)
            acc = fmaf(F2[r * 129 + k], W3T[k * 65 + j], acc);
        F3[o] = fmaxf(acc, 0.0f);
    }
    __syncthreads();
    if (tid < 16) {
        float s0 = 0.f;
        #pragma unroll
        for (int j = 0; j < 64; ++j) s0 += F3[tid*64 + j];
        float mu = s0 * (1.0f / 64.0f);
        float v = 0.f;
        #pragma unroll
        for (int j = 0; j < 64; ++j) { float dd = F3[tid*64 + j] - mu; v = fmaf(dd, dd, v); }
        MU[tid] = mu;
        RS[tid] = rsqrtf(v * (1.0f / 64.0f) + 1e-5f);
    }
    __syncthreads();
    for (int o = tid; o < 1024; o += 128) {
        int r = o >> 6, j = o & 63;
        out[(m0 + r) * 64 + j] = (F3[o] - MU[r]) * RS[r] * ln_g[j] + ln_b[j];
    }
}

// =============================== launch ===============================
extern "C" void kernel_launch(void* const* d_in, const int* in_sizes, int n_in,
                              void* d_out, int out_size)
{
    const float* ttraj = (const float*)d_in[0];
    const float* ntraj = (const float*)d_in[1];
    const float* ang   = (const float*)d_in[2];
    const float* mask  = (const float*)d_in[3];
    const float* Wih_t = (const float*)d_in[4];
    const float* Whh_t = (const float*)d_in[5];
    const float* bih_t = (const float*)d_in[6];
    const float* bhh_t = (const float*)d_in[7];
    const float* Wih_n = (const float*)d_in[8];
    const float* Whh_n = (const float*)d_in[9];
    const float* bih_n = (const float*)d_in[10];
    const float* bhh_n = (const float*)d_in[11];
    const float* W1  = (const float*)d_in[12];
    const float* b1  = (const float*)d_in[13];
    const float* W2  = (const float*)d_in[14];
    const float* b2  = (const float*)d_in[15];
    const float* Wf1 = (const float*)d_in[16];
    const float* bf1 = (const float*)d_in[17];
    const float* Wf2 = (const float*)d_in[18];
    const float* bf2 = (const float*)d_in[19];
    const float* Wf3 = (const float*)d_in[20];
    const float* bf3 = (const float*)d_in[21];
    const float* ln_g = (const float*)d_in[22];
    const float* ln_b = (const float*)d_in[23];
    float* out = (float*)d_out;

    cudaFuncSetAttribute(k1_ngru,   cudaFuncAttributeMaxDynamicSharedMemorySize, H_SMEM);
    cudaFuncSetAttribute(k2_tgru,   cudaFuncAttributeMaxDynamicSharedMemorySize, K2_SMEM);
    cudaFuncSetAttribute(k3_sector, cudaFuncAttributeMaxDynamicSharedMemorySize, K3_SMEM);
    cudaFuncSetAttribute(k5_f1,     cudaFuncAttributeMaxDynamicSharedMemorySize, K5_SMEM);
    cudaFuncSetAttribute(k6_final,  cudaFuncAttributeMaxDynamicSharedMemorySize, K6_SMEM);

    k1_ngru<<<296, 256, H_SMEM>>>(ntraj, Wih_n, Whh_n, bih_n, bhh_n);
    k2_tgru<<<148, 384, K2_SMEM>>>(ttraj, Wih_t, Whh_t, bih_t, bhh_t);
    k3_sector<<<296, 512, K3_SMEM>>>(ttraj, ntraj, ang, mask, W1, b1, W2, b2);
    k5_f1<<<256, 256, K5_SMEM>>>(Wf1, bf1);
    k6_final<<<128, 128, K6_SMEM>>>(Wf2, bf2, Wf3, bf3, ln_g, ln_b, out);
}

// round 17
// speedup vs baseline: 1.2769x; 1.0538x over previous
#include <cuda_runtime.h>
#include <stdint.h>
#include <math.h>

#define BB   2048
#define NNB  64
#define HH   128
#define HN   64
#define NSEQ (BB*NNB)

__device__ float g_nf[NSEQ * HN];        // neighbor GRU features
__device__ float g_tf[BB * HH];          // target GRU features
__device__ float g_enc[BB * 8 * HH];     // per-sector MLP output
__device__ float g_f1[BB * 256];         // first final-MLP layer

// fast activations: hardware tanh (MUFU.TANH), sigmoid via tanh identity
__device__ __forceinline__ float tanh_fast(float x) {
    float y; asm("tanh.approx.f32 %0, %1;" : "=f"(y) : "f"(x)); return y;
}
__device__ __forceinline__ float sigmoid_fast(float x) {
    return fmaf(0.5f, tanh_fast(0.5f * x), 0.5f);
}
__device__ __forceinline__ uint32_t pack_bf2(float lo, float hi) {
    uint32_t r;
    asm("cvt.rn.bf16x2.f32 %0, %1, %2;" : "=r"(r) : "f"(hi), "f"(lo));
    return r;
}
__device__ __forceinline__ float bf_lo(uint32_t u) { return __uint_as_float(u << 16); }
__device__ __forceinline__ float bf_hi(uint32_t u) { return __uint_as_float(u & 0xFFFF0000u); }

__device__ __forceinline__ void mma16816(float* d, const uint32_t* a, uint2 b) {
    asm volatile("mma.sync.aligned.m16n8k16.row.col.f32.bf16.bf16.f32 "
        "{%0,%1,%2,%3}, {%4,%5,%6,%7}, {%8,%9}, {%0,%1,%2,%3};"
        : "+f"(d[0]), "+f"(d[1]), "+f"(d[2]), "+f"(d[3])
        : "r"(a[0]), "r"(a[1]), "r"(a[2]), "r"(a[3]), "r"(b.x), "r"(b.y));
}

// =============== K1: neighbor GRU via mma.sync, single-bf16 gates ===============
// All gates: single bf16 product (Ahi x Whi). h state kept exact as hi+lo pair
// in registers (lo used only for hold reconstruction, never in MMA).
#define H_WHI  0                 // u32[24][4][32][2]  24576 B
#define H_XS   24576             // float2[8][128]      8192 B
#define H_WIH  32768             // float2[192]         1536 B
#define H_BIH  34304             // float[192]           768 B
#define H_BHH  35072             // float[192]           768 B
#define H_SMEM 35840
#define H_NTILE (NSEQ / 128)     // 1024

__global__ __launch_bounds__(256)
void k1_ngru(const float* __restrict__ traj, const float* __restrict__ Wih,
             const float* __restrict__ Whh, const float* __restrict__ bih,
             const float* __restrict__ bhh)
{
    extern __shared__ char sh[];
    uint32_t* WHI = (uint32_t*)(sh + H_WHI);
    float2*   XS2 = (float2*)(sh + H_XS);
    float2*   WIH2= (float2*)(sh + H_WIH);
    float*    BIH = (float*)(sh + H_BIH);
    float*    BHH = (float*)(sh + H_BHH);

    const int tid  = threadIdx.x;
    const int lane = tid & 31;
    const int w    = tid >> 5;
    const int g    = lane >> 2;
    const int tig  = lane & 3;

    for (int e = tid; e < 3072; e += 256) {
        int l = e & 31, jtkt = e >> 5;
        int kt = jtkt & 3, jt = jtkt >> 2;
        int j = 8 * jt + (l >> 2);
        #pragma unroll
        for (int r = 0; r < 2; ++r) {
            int k = 16 * kt + 2 * (l & 3) + 8 * r;
            WHI[e * 2 + r] = pack_bf2(Whh[j * 64 + k], Whh[j * 64 + k + 1]);
        }
    }
    if (tid < 192) {
        WIH2[tid] = ((const float2*)Wih)[tid];
        BIH[tid] = bih[tid];
        BHH[tid] = bhh[tid];
    }
    __syncthreads();

    const int sl = w * 16 + g;

    for (int tile = blockIdx.x; tile < H_NTILE; tile += gridDim.x) {
        __syncthreads();
        {
            int s_ = tid >> 1, q0 = (tid & 1) * 2;
            const float4* tp = (const float4*)(traj + (size_t)(tile * 128 + s_) * 16);
            float4 v0 = tp[q0], v1 = tp[q0 + 1];
            XS2[(2 * q0 + 0) * 128 + s_] = make_float2(v0.x, v0.y);
            XS2[(2 * q0 + 1) * 128 + s_] = make_float2(v0.z, v0.w);
            XS2[(2 * q0 + 2) * 128 + s_] = make_float2(v1.x, v1.y);
            XS2[(2 * q0 + 3) * 128 + s_] = make_float2(v1.z, v1.w);
        }
        __syncthreads();

        uint32_t Ahi[4][4], Alo[4][4], Nhi[4][4], Nlo[4][4];
        #pragma unroll
        for (int kt = 0; kt < 4; ++kt)
            #pragma unroll
            for (int r = 0; r < 4; ++r) { Ahi[kt][r] = 0u; Alo[kt][r] = 0u; }

        for (int t = 0; t < 8; ++t) {
            float2 xA = XS2[t * 128 + sl];
            float2 xB = XS2[t * 128 + sl + 8];
            #pragma unroll 2
            for (int jt = 0; jt < 8; ++jt) {
                float dr[4], dz[4], dn[4];
                {
                    float2 b2 = *(const float2*)&BHH[8 * jt + 2 * tig];
                    dr[0] = b2.x; dr[1] = b2.y; dr[2] = b2.x; dr[3] = b2.y;
                    b2 = *(const float2*)&BHH[64 + 8 * jt + 2 * tig];
                    dz[0] = b2.x; dz[1] = b2.y; dz[2] = b2.x; dz[3] = b2.y;
                    b2 = *(const float2*)&BHH[128 + 8 * jt + 2 * tig];
                    dn[0] = b2.x; dn[1] = b2.y; dn[2] = b2.x; dn[3] = b2.y;
                }
                if (t > 0) {
                    #pragma unroll
                    for (int kt = 0; kt < 4; ++kt) {
                        uint2 bh = *(const uint2*)&WHI[((jt * 4 + kt) * 32 + lane) * 2];
                        mma16816(dr, Ahi[kt], bh);
                    }
                    #pragma unroll
                    for (int kt = 0; kt < 4; ++kt) {
                        uint2 bh = *(const uint2*)&WHI[(((jt + 8) * 4 + kt) * 32 + lane) * 2];
                        mma16816(dz, Ahi[kt], bh);
                    }
                    #pragma unroll
                    for (int kt = 0; kt < 4; ++kt) {
                        uint2 bh = *(const uint2*)&WHI[(((jt + 16) * 4 + kt) * 32 + lane) * 2];
                        mma16816(dn, Ahi[kt], bh);
                    }
                }
                float4 wr4 = *(const float4*)&WIH2[8 * jt + 2 * tig];
                float4 wz4 = *(const float4*)&WIH2[64 + 8 * jt + 2 * tig];
                float4 wn4 = *(const float4*)&WIH2[128 + 8 * jt + 2 * tig];
                float2 br2 = *(const float2*)&BIH[8 * jt + 2 * tig];
                float2 bz2 = *(const float2*)&BIH[64 + 8 * jt + 2 * tig];
                float2 bn2 = *(const float2*)&BIH[128 + 8 * jt + 2 * tig];
                const int kt = jt >> 1;
                #pragma unroll
                for (int rh = 0; rh < 2; ++rh) {
                    float x0 = rh ? xB.x : xA.x;
                    float x1 = rh ? xB.y : xA.y;
                    const int reg = (jt & 1) * 2 + rh;
                    uint32_t uh = Ahi[kt][reg], ul = Alo[kt][reg];
                    float hold0 = bf_lo(uh) + bf_lo(ul);
                    float hold1 = bf_hi(uh) + bf_hi(ul);
                    float hnew0, hnew1;
                    #pragma unroll
                    for (int c = 0; c < 2; ++c) {
                        float hr = dr[rh * 2 + c];
                        float hz = dz[rh * 2 + c];
                        float hn = dn[rh * 2 + c];
                        float wrx = c ? wr4.z : wr4.x, wry = c ? wr4.w : wr4.y;
                        float wzx = c ? wz4.z : wz4.x, wzy = c ? wz4.w : wz4.y;
                        float wnx = c ? wn4.z : wn4.x, wny = c ? wn4.w : wn4.y;
                        float xr = fmaf(x0, wrx, fmaf(x1, wry, c ? br2.y : br2.x));
                        float xz = fmaf(x0, wzx, fmaf(x1, wzy, c ? bz2.y : bz2.x));
                        float xn = fmaf(x0, wnx, fmaf(x1, wny, c ? bn2.y : bn2.x));
                        float r = sigmoid_fast(xr + hr);
                        float z = sigmoid_fast(xz + hz);
                        float n = tanh_fast(fmaf(r, hn, xn));
                        float hold = c ? hold1 : hold0;
                        float h = fmaf(z, hold - n, n);
                        if (c) hnew1 = h; else hnew0 = h;
                    }
                    if (t < 7) {
                        uint32_t nh = pack_bf2(hnew0, hnew1);
                        uint32_t nl = pack_bf2(hnew0 - bf_lo(nh), hnew1 - bf_hi(nh));
                        Nhi[kt][reg] = nh; Nlo[kt][reg] = nl;
                    } else {
                        int seq = tile * 128 + sl + 8 * rh;
                        *(float2*)&g_nf[(size_t)seq * 64 + 8 * jt + 2 * tig] =
                            make_float2(hnew0, hnew1);
                    }
                }
            }
            if (t < 7) {
                #pragma unroll
                for (int kt = 0; kt < 4; ++kt)
                    #pragma unroll
                    for (int r = 0; r < 4; ++r) {
                        Ahi[kt][r] = Nhi[kt][r];
                        Alo[kt][r] = Nlo[kt][r];
                    }
            }
        }
    }
}

// ============================ K2: target GRU ============================
#define K2_WT  0
#define K2_HP  (K2_WT + 128*385)
#define K2_H   (K2_HP + 3*384)
#define K2_X   (K2_H + 384)
#define K2_WIH (K2_X + 48)
#define K2_BIH (K2_WIH + 768)
#define K2_BHH (K2_BIH + 384)
#define K2_SMEM ((K2_BHH + 384) * 4)

__global__ __launch_bounds__(384)
void k2_tgru(const float* __restrict__ traj, const float* __restrict__ Wih,
             const float* __restrict__ Whh, const float* __restrict__ bih,
             const float* __restrict__ bhh)
{
    extern __shared__ float sm[];
    float *WT = sm + K2_WT, *HP = sm + K2_HP, *H = sm + K2_H, *X = sm + K2_X;
    float *WIH = sm + K2_WIH, *BIH = sm + K2_BIH, *BHH = sm + K2_BHH;
    const int tid = threadIdx.x;

    for (int idx = tid; idx < 384*128; idx += 384)
        WT[(idx & 127) * 385 + (idx >> 7)] = Whh[idx];
    for (int idx = tid; idx < 768; idx += 384) WIH[idx] = Wih[idx];
    BIH[tid] = bih[tid]; BHH[tid] = bhh[tid];
    __syncthreads();

    const int s = tid >> 7, i = tid & 127;

    for (int tile = blockIdx.x; tile < (BB + 2) / 3; tile += gridDim.x) {
        const int seq0 = tile * 3;
        __syncthreads();
        if (tid < 48) {
            int sq = seq0 + tid / 16;
            X[tid] = (sq < BB) ? traj[sq * 16 + (tid & 15)] : 0.0f;
        }
        H[tid] = 0.0f;
        __syncthreads();

        for (int t = 0; t < 8; ++t) {
            {
                float b = BHH[tid];
                float a0 = b, a1 = b, a2 = b;
                #pragma unroll
                for (int k = 0; k < 128; k += 4) {
                    float4 h0 = *reinterpret_cast<const float4*>(H + k);
                    float4 h1 = *reinterpret_cast<const float4*>(H + 128 + k);
                    float4 h2 = *reinterpret_cast<const float4*>(H + 256 + k);
                    float w0 = WT[(k  )*385+tid], w1 = WT[(k+1)*385+tid];
                    float w2 = WT[(k+2)*385+tid], w3 = WT[(k+3)*385+tid];
                    a0 = fmaf(w0,h0.x,fmaf(w1,h0.y,fmaf(w2,h0.z,fmaf(w3,h0.w,a0))));
                    a1 = fmaf(w0,h1.x,fmaf(w1,h1.y,fmaf(w2,h1.z,fmaf(w3,h1.w,a1))));
                    a2 = fmaf(w0,h2.x,fmaf(w1,h2.y,fmaf(w2,h2.z,fmaf(w3,h2.w,a2))));
                }
                HP[tid] = a0; HP[384 + tid] = a1; HP[768 + tid] = a2;
            }
            __syncthreads();
            {
                float x0 = X[s*16 + t*2], x1 = X[s*16 + t*2 + 1];
                float xr = fmaf(x0, WIH[2*i],        fmaf(x1, WIH[2*i+1],        BIH[i]));
                float xz = fmaf(x0, WIH[2*(128+i)],  fmaf(x1, WIH[2*(128+i)+1],  BIH[128+i]));
                float xn = fmaf(x0, WIH[2*(256+i)],  fmaf(x1, WIH[2*(256+i)+1],  BIH[256+i]));
                float r = sigmoid_fast(xr + HP[s*384 + i]);
                float z = sigmoid_fast(xz + HP[s*384 + 128 + i]);
                float n = tanh_fast(fmaf(r, HP[s*384 + 256 + i], xn));
                H[s*128 + i] = fmaf(z, H[s*128 + i] - n, n);
            }
            __syncthreads();
        }
        int sq = seq0 + s;
        if (sq < BB) g_tf[sq * 128 + i] = H[s*128 + i];
    }
}

// =================== K3: sector features + per-sector MLP ===================
#define K3_W1T  0
#define K3_W2T  (K3_W1T + 68*129)
#define K3_NF   (K3_W2T + 128*129)
#define K3_FEAT (K3_NF + 4096)
#define K3_H1   (K3_FEAT + 8*68)
#define K3_WSUM (K3_H1 + 1024)
#define K3_WV   (K3_WSUM + 8)
#define K3_DIST (K3_WV + 64)
#define K3_VAL  (K3_DIST + 64)
#define K3_V0   (K3_VAL + 64)
#define K3_V1   (K3_V0 + 64)
#define K3_SMEM ((K3_V1 + 64) * 4)

__global__ __launch_bounds__(512)
void k3_sector(const float* __restrict__ ttraj, const float* __restrict__ ntraj,
               const float* __restrict__ ang, const float* __restrict__ mask,
               const float* __restrict__ W1, const float* __restrict__ b1,
               const float* __restrict__ W2, const float* __restrict__ b2)
{
    extern __shared__ float smf[];
    __shared__ int SID[64];
    float *W1T = smf + K3_W1T, *W2T = smf + K3_W2T, *NF = smf + K3_NF;
    float *FEAT = smf + K3_FEAT, *H1 = smf + K3_H1, *WSUM = smf + K3_WSUM;
    float *WV = smf + K3_WV, *DIST = smf + K3_DIST, *VAL = smf + K3_VAL;
    float *V0 = smf + K3_V0, *V1 = smf + K3_V1;
    const int tid = threadIdx.x;

    for (int idx = tid; idx < 128*68; idx += 512)
        W1T[(idx % 68) * 129 + (idx / 68)] = W1[idx];
    for (int idx = tid; idx < 128*128; idx += 512)
        W2T[(idx & 127) * 129 + (idx >> 7)] = W2[idx];
    __syncthreads();

    const int s = tid >> 6, i = tid & 63;

    for (int b = blockIdx.x; b < BB; b += gridDim.x) {
        __syncthreads();
        for (int idx = tid; idx < 4096; idx += 512)
            NF[idx] = g_nf[b * 4096 + idx];
        if (tid < 64) {
            const float* base = ntraj + (size_t)(b * 64 + tid) * 16;
            float px = base[14], py = base[15];
            float dx = px - ttraj[b*16 + 14], dy = py - ttraj[b*16 + 15];
            float d = sqrtf(dx*dx + dy*dy);
            DIST[tid] = d;
            V0[tid] = px - base[12];
            V1[tid] = py - base[13];
            int sid = (int)(ang[b*64 + tid] * 1.27323954473516f);
            SID[tid] = min(max(sid, 0), 7);
            float vf = (mask[b*64 + tid] > 0.0f) ? 1.0f : 0.0f;
            VAL[tid] = vf;
            WV[tid] = __expf(-d * 0.1f) * vf;
        }
        __syncthreads();
        if (tid < 8) {
            float cnt = 0.f, dsum = 0.f, v0 = 0.f, v1 = 0.f, ws = 0.f;
            for (int n = 0; n < 64; ++n) {
                bool in = (SID[n] == tid);
                float m = in ? VAL[n] : 0.0f;
                cnt += m; dsum += m * DIST[n]; v0 += m * V0[n]; v1 += m * V1[n];
                ws += in ? WV[n] : 0.0f;
            }
            float safe = fmaxf(cnt, 1.0f);
            bool ne = cnt > 0.0f;
            FEAT[tid*68 + 0] = cnt;
            FEAT[tid*68 + 1] = ne ? dsum / safe : 0.0f;
            FEAT[tid*68 + 2] = ne ? v0 / safe : 0.0f;
            FEAT[tid*68 + 3] = ne ? v1 / safe : 0.0f;
            WSUM[tid] = ws + 1e-8f;
        }
        __syncthreads();
        {
            float acc = 0.0f;
            for (int n = 0; n < 64; ++n) {
                float wm = (SID[n] == s) ? WV[n] : 0.0f;
                acc = fmaf(wm, NF[n*64 + i], acc);
            }
            FEAT[s*68 + 4 + i] = acc / WSUM[s];
        }
        __syncthreads();
        for (int o = tid; o < 1024; o += 512) {
            int os = o >> 7, oj = o & 127;
            float acc = b1[oj];
            #pragma unroll
            for (int k = 0; k < 68; ++k)
                acc = fmaf(FEAT[os*68 + k], W1T[k*129 + oj], acc);
            H1[os*128 + oj] = fmaxf(acc, 0.0f);
        }
        __syncthreads();
        for (int o = tid; o < 1024; o += 512) {
            int os = o >> 7, oj = o & 127;
            float acc = b2[oj];
            #pragma unroll
            for (int k = 0; k < 128; ++k)
                acc = fmaf(H1[os*128 + k], W2T[k*129 + oj], acc);
            g_enc[b * 1024 + o] = fmaxf(acc, 0.0f);
        }
    }
}

// =================== K5: f1 = relu([tf,enc] @ Wf1.T + bf1) ===================
#define K5_PAD 12
#define K5_SMEM ((32*257 + 32*K5_PAD) * 4)

__global__ __launch_bounds__(256)
void k5_f1(const float* __restrict__ Wf1, const float* __restrict__ bf1)
{
    extern __shared__ float k5s[];
    float* Wsh = k5s;
    float* Ash = k5s + 32 * 257;

    const int tid = threadIdx.x;
    const int m0 = blockIdx.x * 8;
    const int jb = tid >> 5, kk = tid & 31;

    float acc[8];
    float bv = bf1[tid];
    #pragma unroll
    for (int r = 0; r < 8; ++r) acc[r] = bv;

    float wreg[32];
    float areg;

    #pragma unroll
    for (int rr = 0; rr < 32; ++rr)
        wreg[rr] = Wf1[(jb + rr * 8) * 1152 + kk];
    areg = g_tf[(m0 + jb) * 128 + kk];

    for (int c = 0; c < 36; ++c) {
        __syncthreads();
        #pragma unroll
        for (int rr = 0; rr < 32; ++rr)
            Wsh[kk * 257 + jb + rr * 8] = wreg[rr];
        Ash[kk * K5_PAD + jb] = areg;
        __syncthreads();
        if (c < 35) {
            const int k0 = (c + 1) * 32;
            #pragma unroll
            for (int rr = 0; rr < 32; ++rr)
                wreg[rr] = Wf1[(jb + rr * 8) * 1152 + k0 + kk];
            int gk = k0 + kk;
            areg = (gk < 128) ? g_tf[(m0 + jb) * 128 + gk]
                              : g_enc[(m0 + jb) * 1024 + gk - 128];
        }
        #pragma unroll
        for (int q = 0; q < 32; ++q) {
            float w = Wsh[q * 257 + tid];
            float4 a0 = *reinterpret_cast<const float4*>(&Ash[q * K5_PAD]);
            float4 a1 = *reinterpret_cast<const float4*>(&Ash[q * K5_PAD + 4]);
            acc[0]=fmaf(w,a0.x,acc[0]); acc[1]=fmaf(w,a0.y,acc[1]);
            acc[2]=fmaf(w,a0.z,acc[2]); acc[3]=fmaf(w,a0.w,acc[3]);
            acc[4]=fmaf(w,a1.x,acc[4]); acc[5]=fmaf(w,a1.y,acc[5]);
            acc[6]=fmaf(w,a1.z,acc[6]); acc[7]=fmaf(w,a1.w,acc[7]);
        }
    }
    #pragma unroll
    for (int r = 0; r < 8; ++r)
        g_f1[(m0 + r) * 256 + tid] = fmaxf(acc[r], 0.0f);
}

// =================== K6: f2, f3, LayerNorm ===================
#define K6_W2T 0
#define K6_W3T (K6_W2T + 256*129)
#define K6_F1  (K6_W3T + 128*65)
#define K6_F2  (K6_F1 + 16*257)
#define K6_F3  (K6_F2 + 16*129)
#define K6_MU  (K6_F3 + 1024)
#define K6_RS  (K6_MU + 16)
#define K6_SMEM ((K6_RS + 16) * 4)

__global__ __launch_bounds__(128)
void k6_final(const float* __restrict__ Wf2, const float* __restrict__ bf2,
              const float* __restrict__ Wf3, const float* __restrict__ bf3,
              const float* __restrict__ ln_g, const float* __restrict__ ln_b,
              float* __restrict__ out)
{
    extern __shared__ float smf[];
    float *W2T = smf + K6_W2T, *W3T = smf + K6_W3T, *F1 = smf + K6_F1;
    float *F2 = smf + K6_F2, *F3 = smf + K6_F3, *MU = smf + K6_MU, *RS = smf + K6_RS;
    const int tid = threadIdx.x;
    const int m0 = blockIdx.x * 16;

    for (int idx = tid; idx < 128*256; idx += 128)
        W2T[(idx & 255) * 129 + (idx >> 8)] = Wf2[idx];
    for (int idx = tid; idx < 64*128; idx += 128)
        W3T[(idx & 127) * 65 + (idx >> 7)] = Wf3[idx];
    for (int idx = tid; idx < 16*256; idx += 128)
        F1[(idx >> 8) * 257 + (idx & 255)] = g_f1[m0 * 256 + idx];
    __syncthreads();

    {
        float acc[16];
        float bv = bf2[tid];
        #pragma unroll
        for (int r = 0; r < 16; ++r) acc[r] = bv;
        for (int k = 0; k < 256; ++k) {
            float w = W2T[k * 129 + tid];
            #pragma unroll
            for (int r = 0; r < 16; ++r)
                acc[r] = fmaf(F1[r * 257 + k], w, acc[r]);
        }
        #pragma unroll
        for (int r = 0; r < 16; ++r)
            F2[r * 129 + tid] = fmaxf(acc[r], 0.0f);
    }
    __syncthreads();
    for (int o = tid; o < 1024; o += 128) {
        int r = o >> 6, j = o & 63;
        float acc = bf3[j];
        #pragma unroll
        for (int k = 0; k < 128; ++k)
            acc = fmaf(F2[r * 129 + k], W3T[k * 65 + j], acc);
        F3[o] = fmaxf(acc, 0.0f);
    }
    __syncthreads();
    if (tid < 16) {
        float s0 = 0.f;
        #pragma unroll
        for (int j = 0; j < 64; ++j) s0 += F3[tid*64 + j];
        float mu = s0 * (1.0f / 64.0f);
        float v = 0.f;
        #pragma unroll
        for (int j = 0; j < 64; ++j) { float dd = F3[tid*64 + j] - mu; v = fmaf(dd, dd, v); }
        MU[tid] = mu;
        RS[tid] = rsqrtf(v * (1.0f / 64.0f) + 1e-5f);
    }
    __syncthreads();
    for (int o = tid; o < 1024; o += 128) {
        int r = o >> 6, j = o & 63;
        out[(m0 + r) * 64 + j] = (F3[o] - MU[r]) * RS[r] * ln_g[j] + ln_b[j];
    }
}

// =============================== launch ===============================
extern "C" void kernel_launch(void* const* d_in, const int* in_sizes, int n_in,
                              void* d_out, int out_size)
{
    const float* ttraj = (const float*)d_in[0];
    const float* ntraj = (const float*)d_in[1];
    const float* ang   = (const float*)d_in[2];
    const float* mask  = (const float*)d_in[3];
    const float* Wih_t = (const float*)d_in[4];
    const float* Whh_t = (const float*)d_in[5];
    const float* bih_t = (const float*)d_in[6];
    const float* bhh_t = (const float*)d_in[7];
    const float* Wih_n = (const float*)d_in[8];
    const float* Whh_n = (const float*)d_in[9];
    const float* bih_n = (const float*)d_in[10];
    const float* bhh_n = (const float*)d_in[11];
    const float* W1  = (const float*)d_in[12];
    const float* b1  = (const float*)d_in[13];
    const float* W2  = (const float*)d_in[14];
    const float* b2  = (const float*)d_in[15];
    const float* Wf1 = (const float*)d_in[16];
    const float* bf1 = (const float*)d_in[17];
    const float* Wf2 = (const float*)d_in[18];
    const float* bf2 = (const float*)d_in[19];
    const float* Wf3 = (const float*)d_in[20];
    const float* bf3 = (const float*)d_in[21];
    const float* ln_g = (const float*)d_in[22];
    const float* ln_b = (const float*)d_in[23];
    float* out = (float*)d_out;

    cudaFuncSetAttribute(k1_ngru,   cudaFuncAttributeMaxDynamicSharedMemorySize, H_SMEM);
    cudaFuncSetAttribute(k2_tgru,   cudaFuncAttributeMaxDynamicSharedMemorySize, K2_SMEM);
    cudaFuncSetAttribute(k3_sector, cudaFuncAttributeMaxDynamicSharedMemorySize, K3_SMEM);
    cudaFuncSetAttribute(k5_f1,     cudaFuncAttributeMaxDynamicSharedMemorySize, K5_SMEM);
    cudaFuncSetAttribute(k6_final,  cudaFuncAttributeMaxDynamicSharedMemorySize, K6_SMEM);

    k1_ngru<<<296, 256, H_SMEM>>>(ntraj, Wih_n, Whh_n, bih_n, bhh_n);
    k2_tgru<<<148, 384, K2_SMEM>>>(ttraj, Wih_t, Whh_t, bih_t, bhh_t);
    k3_sector<<<296, 512, K3_SMEM>>>(ttraj, ntraj, ang, mask, W1, b1, W2, b2);
    k5_f1<<<256, 256, K5_SMEM>>>(Wf1, bf1);
    k6_final<<<128, 128, K6_SMEM>>>(Wf2, bf2, Wf3, bf3, ln_g, ln_b, out);
}